// round 1
// baseline (speedup 1.0000x reference)
#include <cuda_runtime.h>
#include <cuda_bf16.h>
#include <math.h>

// ---------------- problem constants ----------------
#define BB   256
#define LL   201
#define DD   1536
#define HH   64
#define NHD  2      // heads
#define DH   32     // head dim
#define FF   256
#define NTOT (BB*LL)          // 51456

// output offsets (float elements)
#define OFF1 0                          // prec_vec[:, :-1, :]  (256,200,64)
#define OFF2 3276800                    // target_pos            (256,200,64)
#define OFF3 6553600                    // target_neg            (256,200,64)
#define OFF4 9830400                    // concat(emb, prec)     (256,201,128)
#define SIMO 16416768                   // similarity scalar

// ---------------- scratch ----------------
__device__ float g_T1  [NTOT*HH];
__device__ float g_Tneg[NTOT*HH];
__device__ float g_emb [NTOT*HH];
__device__ float g_negE[NTOT*HH];
__device__ float g_x   [NTOT*HH];
__device__ float g_tmp [NTOT*HH];
__device__ float g_qkv [NTOT*192];
__device__ float g_attn[NTOT*HH];
__device__ float g_ff1 [NTOT*FF];
__device__ float g_xsum[BB*DD];
__device__ float g_uon [BB*HH];
__device__ float g_part[6432];

// ---------------- helpers ----------------
__device__ __forceinline__ float wsum(float v){
    #pragma unroll
    for (int o = 16; o; o >>= 1) v += __shfl_xor_sync(0xffffffffu, v, o);
    return v;
}
__device__ __forceinline__ float wmaxf(float v){
    #pragma unroll
    for (int o = 16; o; o >>= 1) v = fmaxf(v, __shfl_xor_sync(0xffffffffu, v, o));
    return v;
}
__device__ __forceinline__ float gelu_f(float x){
    float x3 = x*x*x;
    return 0.5f*x*(1.f + tanhf(0.7978845608028654f*(x + 0.044715f*x3)));
}

// ---------------- big GEMM: (N,1536) @ (1536,64) + bias ----------------
__global__ void gemm_big(const float* __restrict__ X, const float* __restrict__ W,
                         const float* __restrict__ bias, float* __restrict__ out)
{
    __shared__ float Xs[64][33];
    __shared__ float Ws[32*64];
    int row0 = blockIdx.x * 64;
    int t = threadIdx.x;
    int tx = t & 15, ty = t >> 4;
    float acc[4][4];
    #pragma unroll
    for (int i = 0; i < 4; i++)
        #pragma unroll
        for (int j = 0; j < 4; j++) acc[i][j] = 0.f;

    for (int kc = 0; kc < DD; kc += 32) {
        #pragma unroll
        for (int it = 0; it < 2; it++) {
            int i = t + it*256;           // 512 float4 total
            int r = i >> 3, ks = (i & 7) << 2;
            float4 v = *(const float4*)(X + (size_t)(row0 + r)*DD + kc + ks);
            Xs[r][ks] = v.x; Xs[r][ks+1] = v.y; Xs[r][ks+2] = v.z; Xs[r][ks+3] = v.w;
        }
        #pragma unroll
        for (int it = 0; it < 2; it++) {
            int i = t + it*256;
            ((float4*)Ws)[i] = ((const float4*)(W + (size_t)kc*64))[i];
        }
        __syncthreads();
        #pragma unroll
        for (int k = 0; k < 32; k++) {
            float4 b4 = *(const float4*)(Ws + k*64 + tx*4);
            float a0 = Xs[ty*4+0][k], a1 = Xs[ty*4+1][k], a2 = Xs[ty*4+2][k], a3 = Xs[ty*4+3][k];
            acc[0][0] += a0*b4.x; acc[0][1] += a0*b4.y; acc[0][2] += a0*b4.z; acc[0][3] += a0*b4.w;
            acc[1][0] += a1*b4.x; acc[1][1] += a1*b4.y; acc[1][2] += a1*b4.z; acc[1][3] += a1*b4.w;
            acc[2][0] += a2*b4.x; acc[2][1] += a2*b4.y; acc[2][2] += a2*b4.z; acc[2][3] += a2*b4.w;
            acc[3][0] += a3*b4.x; acc[3][1] += a3*b4.y; acc[3][2] += a3*b4.z; acc[3][3] += a3*b4.w;
        }
        __syncthreads();
    }
    float4 bb = *(const float4*)(bias + tx*4);
    #pragma unroll
    for (int i = 0; i < 4; i++) {
        float4 o;
        o.x = acc[i][0] + bb.x; o.y = acc[i][1] + bb.y;
        o.z = acc[i][2] + bb.z; o.w = acc[i][3] + bb.w;
        *(float4*)(out + (size_t)(row0 + ty*4 + i)*64 + tx*4) = o;
    }
}

// ---------------- generic small GEMM (K,M) with W resident in smem ----------------
template<int K, int M, bool GELU, bool RES>
__global__ void gemm_small(const float* __restrict__ X, const float* __restrict__ W,
                           const float* __restrict__ bias, const float* __restrict__ res,
                           float* __restrict__ out, int N)
{
    extern __shared__ float sm[];
    float* Ws = sm;            // K*M
    float* Xs = sm + K*M;      // 32*K
    const int RT = 32;
    int row0 = blockIdx.x * RT;
    int t = threadIdx.x;

    for (int i = t; i < K*M/4; i += 256)
        ((float4*)Ws)[i] = ((const float4*)W)[i];
    for (int i = t; i < RT*K/4; i += 256) {
        int r = (i*4) / K;
        int k = (i*4) % K;
        int gr = row0 + r;
        float4 v = (gr < N) ? ((const float4*)(X + (size_t)gr*K))[k/4]
                            : make_float4(0.f,0.f,0.f,0.f);
        ((float4*)Xs)[i] = v;
    }
    __syncthreads();

    const int CH = RT*M/1024;
    #pragma unroll
    for (int ch = 0; ch < CH; ch++) {
        int o = t*4 + ch*1024;
        int r = o / M, c = o % M;
        float4 acc = make_float4(0.f,0.f,0.f,0.f);
        const float* xr = Xs + r*K;
        #pragma unroll 8
        for (int k = 0; k < K; k++) {
            float x = xr[k];
            float4 w = ((const float4*)(Ws + k*M))[c >> 2];
            acc.x += x*w.x; acc.y += x*w.y; acc.z += x*w.z; acc.w += x*w.w;
        }
        int gr = row0 + r;
        if (gr < N) {
            float4 b4 = ((const float4*)bias)[c >> 2];
            acc.x += b4.x; acc.y += b4.y; acc.z += b4.z; acc.w += b4.w;
            if (RES) {
                float4 r4 = ((const float4*)(res + (size_t)gr*M))[c >> 2];
                acc.x += r4.x; acc.y += r4.y; acc.z += r4.z; acc.w += r4.w;
            }
            if (GELU) {
                acc.x = gelu_f(acc.x); acc.y = gelu_f(acc.y);
                acc.z = gelu_f(acc.z); acc.w = gelu_f(acc.w);
            }
            ((float4*)(out + (size_t)gr*M))[c >> 2] = acc;
        }
    }
}

// ---------------- LayerNorm over H=64 (one warp per row) ----------------
__global__ void ln_kernel(const float* __restrict__ in, const float* __restrict__ pos,
                          const float* __restrict__ g, const float* __restrict__ b,
                          float* __restrict__ out, int N)
{
    int row = blockIdx.x * 8 + (threadIdx.x >> 5);
    int lane = threadIdx.x & 31;
    if (row >= N) return;
    int l = row % LL;
    float v0 = in[(size_t)row*64 + lane];
    float v1 = in[(size_t)row*64 + 32 + lane];
    if (pos) { v0 += pos[l*64 + lane]; v1 += pos[l*64 + 32 + lane]; }
    float mean = wsum(v0 + v1) * (1.f/64.f);
    float d0 = v0 - mean, d1 = v1 - mean;
    float var = wsum(d0*d0 + d1*d1) * (1.f/64.f);
    float inv = rsqrtf(var + 1e-5f);
    out[(size_t)row*64 + lane]      = d0*inv*g[lane]      + b[lane];
    out[(size_t)row*64 + 32 + lane] = d1*inv*g[lane+32]   + b[lane+32];
}

// ---------------- attention: one block per (b,head), K/V in smem ----------------
__global__ void attn_kernel(const float* __restrict__ qkv, const int* __restrict__ mask,
                            float* __restrict__ O)
{
    extern __shared__ float sm[];
    float* Ks = sm;                 // 201*33
    float* Vs = Ks + 201*33;        // 201*33
    float* Sc = Vs + 201*33;        // 8*224
    float* Qs = Sc + 8*224;         // 8*32
    float* Ms = Qs + 8*32;          // 201

    int bh = blockIdx.x;
    int b = bh >> 1, h = bh & 1;
    const float* base = qkv + (size_t)b*LL*192;
    int t = threadIdx.x;

    for (int i = t; i < LL*32; i += 256) {
        int j = i >> 5, d = i & 31;
        Ks[j*33 + d] = base[j*192 + 64  + h*32 + d];
        Vs[j*33 + d] = base[j*192 + 128 + h*32 + d];
    }
    for (int i = t; i < LL; i += 256) Ms[i] = (float)mask[b*LL + i];
    __syncthreads();

    int w = t >> 5, lane = t & 31;
    float* sc = Sc + w*224;
    for (int l = w; l < LL; l += 8) {
        Qs[w*32 + lane] = base[l*192 + h*32 + lane];
        __syncwarp();
        for (int j0 = 0; j0 < LL; j0 += 32) {
            int j = j0 + lane;
            if (j < LL) {
                float dot = 0.f;
                #pragma unroll
                for (int d = 0; d < 32; d++) dot += Qs[w*32 + d] * Ks[j*33 + d];
                dot *= 0.17677669529663687f; // 1/sqrt(32)
                bool allowed = (j <= l) && (Ms[j] > 0.f);
                sc[j] = dot + (allowed ? 0.f : -1e9f);
            }
        }
        __syncwarp();
        float mx = -INFINITY;
        for (int j = lane; j < LL; j += 32) mx = fmaxf(mx, sc[j]);
        mx = wmaxf(mx);
        float s = 0.f;
        for (int j = lane; j < LL; j += 32) { float e = __expf(sc[j]-mx); sc[j] = e; s += e; }
        s = wsum(s);
        float inv = 1.f / s;
        __syncwarp();
        float acc = 0.f;
        for (int j = 0; j < LL; j++) acc += sc[j] * Vs[j*33 + lane];
        O[((size_t)b*LL + l)*64 + h*32 + lane] = acc * inv;
        __syncwarp();
    }
}

// ---------------- masked sum of interaction_list over L ----------------
__global__ void xsum_kernel(const float* __restrict__ X, const int* __restrict__ mask,
                            float* __restrict__ Xsum)
{
    int b = blockIdx.x;
    int d = blockIdx.y * 256 + threadIdx.x;
    const float* xb = X + (size_t)b*LL*DD;
    float acc = 0.f;
    for (int l = 0; l < LL; l++)
        if (mask[b*LL + l]) acc += xb[(size_t)l*DD + d];
    Xsum[(size_t)b*DD + d] = acc;
}

// ---------------- collapsed GNN: u_on[b] = relu(meanG+bg1)@wg2 ----------------
__global__ void gnn_kernel(const float* __restrict__ Xsum, const int* __restrict__ mask,
                           const float* __restrict__ wg1, const float* __restrict__ bg1,
                           const float* __restrict__ wg2, float* __restrict__ uon)
{
    __shared__ float xs[DD];
    __shared__ float h1[FF];
    __shared__ int   Scnt;
    int b = blockIdx.x, t = threadIdx.x;
    for (int i = t; i < DD; i += 256) xs[i] = Xsum[(size_t)b*DD + i];
    int cnt = 0;
    for (int l = t; l < LL; l += 256) cnt += mask[b*LL + l];
    if (t == 0) Scnt = 0;
    __syncthreads();
    if (cnt) atomicAdd(&Scnt, cnt);
    __syncthreads();
    float S = (float)Scnt;
    float scale = S > 0.f ? 1.f/S : 0.f;
    float mg = 0.f;
    for (int k = 0; k < DD; k++) mg += xs[k] * wg1[(size_t)k*FF + t];
    h1[t] = fmaxf(mg*scale + bg1[t], 0.f);
    __syncthreads();
    if (t < 64) {
        float u = 0.f;
        for (int f = 0; f < FF; f++) u += h1[f] * wg2[(size_t)f*64 + t];
        uon[b*64 + t] = (S > 0.f) ? u : 0.f;
    }
}

// ---------------- similarity ----------------
__global__ void sim_kernel(const float* __restrict__ emb, const float* __restrict__ uon,
                           const float* __restrict__ bg2, const int* __restrict__ mask,
                           float* __restrict__ partial)
{
    __shared__ float ps[8];
    int w = threadIdx.x >> 5, lane = threadIdx.x & 31;
    int row = blockIdx.x * 8 + w;
    float c = 0.f;
    if (row < NTOT) {
        int b = row / LL;
        float m = (float)mask[row];
        float e0 = emb[(size_t)row*64 + lane];
        float e1 = emb[(size_t)row*64 + 32 + lane];
        float g0 = m*uon[b*64 + lane]      + bg2[lane];
        float g1 = m*uon[b*64 + 32 + lane] + bg2[lane+32];
        float num = wsum(e0*g0 + e1*g1);
        float na  = wsum(e0*e0 + e1*e1);
        float nb  = wsum(g0*g0 + g1*g1);
        na = fmaxf(sqrtf(na), 1e-8f);
        nb = fmaxf(sqrtf(nb), 1e-8f);
        c = num / (na*nb);
    }
    if (lane == 0) ps[w] = c;
    __syncthreads();
    if (threadIdx.x == 0) {
        float s = 0.f;
        #pragma unroll
        for (int i = 0; i < 8; i++) s += ps[i];
        partial[blockIdx.x] = s;
    }
}

__global__ void sim_reduce(const float* __restrict__ partial, float* __restrict__ out)
{
    __shared__ float smem[256];
    float s = 0.f;
    for (int i = threadIdx.x; i < 6432; i += 256) s += partial[i];
    smem[threadIdx.x] = s;
    __syncthreads();
    for (int o = 128; o; o >>= 1) {
        if (threadIdx.x < o) smem[threadIdx.x] += smem[threadIdx.x + o];
        __syncthreads();
    }
    if (threadIdx.x == 0) out[0] = smem[0] / (float)(LL*BB);
}

// ---------------- output assembly ----------------
__global__ void out_kernel(const float* __restrict__ emb, const float* __restrict__ x,
                           const float* __restrict__ negE, float* __restrict__ out)
{
    int row = blockIdx.x;
    int t = threadIdx.x;   // 64
    int b = row / LL, l = row % LL;
    float e = emb[(size_t)row*64 + t];
    float xv = x[(size_t)row*64 + t];
    out[OFF4 + (size_t)row*128 + t]      = e;
    out[OFF4 + (size_t)row*128 + 64 + t] = xv;
    if (l < LL-1) {
        size_t r200 = (size_t)b*(LL-1) + l;
        out[OFF1 + r200*64 + t] = xv;
        out[OFF2 + r200*64 + t] = emb[((size_t)b*LL + l + 1)*64 + t];
        out[OFF3 + r200*64 + t] = negE[(size_t)row*64 + t];
    }
}

// ---------------- host ----------------
template <typename T>
static float* symaddr(T& sym){ void* p = nullptr; cudaGetSymbolAddress(&p, sym); return (float*)p; }

extern "C" void kernel_launch(void* const* d_in, const int* in_sizes, int n_in,
                              void* d_out, int out_size)
{
    const float* inter = (const float*)d_in[0];
    const float* neg   = (const float*)d_in[1];
    const float* fc_w  = (const float*)d_in[2];
    const float* fc_b  = (const float*)d_in[3];
    const float* mlp_w = (const float*)d_in[4];
    const float* mlp_b = (const float*)d_in[5];
    const float* pos   = (const float*)d_in[6];
    const float* ln0g  = (const float*)d_in[7];
    const float* ln0b  = (const float*)d_in[8];
    const float* wqkv  = (const float*)d_in[9];
    const float* bqkv  = (const float*)d_in[10];
    const float* wo    = (const float*)d_in[11];
    const float* bo    = (const float*)d_in[12];
    const float* ln1g  = (const float*)d_in[13];
    const float* ln1b  = (const float*)d_in[14];
    const float* w1    = (const float*)d_in[15];
    const float* b1    = (const float*)d_in[16];
    const float* w2    = (const float*)d_in[17];
    const float* b2    = (const float*)d_in[18];
    const float* ln2g  = (const float*)d_in[19];
    const float* ln2b  = (const float*)d_in[20];
    const float* wg1   = (const float*)d_in[21];
    const float* bg1   = (const float*)d_in[22];
    const float* wg2   = (const float*)d_in[23];
    const float* bg2   = (const float*)d_in[24];
    const int*   mask  = (const int*)d_in[25];
    float* out = (float*)d_out;

    float* T1   = symaddr(g_T1);
    float* Tneg = symaddr(g_Tneg);
    float* emb  = symaddr(g_emb);
    float* negE = symaddr(g_negE);
    float* x    = symaddr(g_x);
    float* tmp  = symaddr(g_tmp);
    float* qkvb = symaddr(g_qkv);
    float* attO = symaddr(g_attn);
    float* ff1  = symaddr(g_ff1);
    float* Xsum = symaddr(g_xsum);
    float* uon  = symaddr(g_uon);
    float* part = symaddr(g_part);

    const int smem_qkv  = (64*192 + 32*64) * 4;   // 57344
    const int smem_mlp  = (64*64  + 32*64) * 4;   // 24576
    const int smem_w1   = (64*256 + 32*64) * 4;   // 73728
    const int smem_w2   = (256*64 + 32*256) * 4;  // 98304
    const int smem_attn = (201*33*2 + 8*224 + 8*32 + 201) * 4; // 62060

    cudaFuncSetAttribute((const void*)gemm_small<64,192,false,false>,
                         cudaFuncAttributeMaxDynamicSharedMemorySize, smem_qkv);
    cudaFuncSetAttribute((const void*)gemm_small<64,256,true,false>,
                         cudaFuncAttributeMaxDynamicSharedMemorySize, smem_w1);
    cudaFuncSetAttribute((const void*)gemm_small<256,64,false,true>,
                         cudaFuncAttributeMaxDynamicSharedMemorySize, smem_w2);
    cudaFuncSetAttribute((const void*)attn_kernel,
                         cudaFuncAttributeMaxDynamicSharedMemorySize, smem_attn);

    const int GB = NTOT/64;    // 804
    const int GS = NTOT/32;    // 1608
    const int GL = NTOT/8;     // 6432

    // embedding towers
    gemm_big<<<GB, 256>>>(inter, fc_w, fc_b, T1);
    gemm_big<<<GB, 256>>>(neg,   fc_w, fc_b, Tneg);
    gemm_small<64,64,true,false><<<GS, 256, smem_mlp>>>(T1,   mlp_w, mlp_b, nullptr, emb,  NTOT);
    gemm_small<64,64,true,false><<<GS, 256, smem_mlp>>>(Tneg, mlp_w, mlp_b, nullptr, negE, NTOT);

    // collapsed GNN + similarity
    xsum_kernel<<<dim3(BB, DD/256), 256>>>(inter, mask, Xsum);
    gnn_kernel<<<BB, 256>>>(Xsum, mask, wg1, bg1, wg2, uon);
    sim_kernel<<<GL, 256>>>(emb, uon, bg2, mask, part);
    sim_reduce<<<1, 256>>>(part, out + SIMO);

    // encoder
    ln_kernel<<<GL, 256>>>(emb, pos, ln0g, ln0b, x, NTOT);
    for (int i = 0; i < 2; i++) {
        gemm_small<64,192,false,false><<<GS, 256, smem_qkv>>>(x, wqkv + (size_t)i*64*192,
                                                              bqkv + i*192, nullptr, qkvb, NTOT);
        attn_kernel<<<BB*NHD, 256, smem_attn>>>(qkvb, mask, attO);
        gemm_small<64,64,false,true><<<GS, 256, smem_mlp>>>(attO, wo + (size_t)i*64*64,
                                                            bo + i*64, x, tmp, NTOT);
        ln_kernel<<<GL, 256>>>(tmp, nullptr, ln1g + i*64, ln1b + i*64, x, NTOT);
        gemm_small<64,256,true,false><<<GS, 256, smem_w1>>>(x, w1 + (size_t)i*64*256,
                                                            b1 + i*256, nullptr, ff1, NTOT);
        gemm_small<256,64,false,true><<<GS, 256, smem_w2>>>(ff1, w2 + (size_t)i*256*64,
                                                            b2 + i*64, x, tmp, NTOT);
        ln_kernel<<<GL, 256>>>(tmp, nullptr, ln2g + i*64, ln2b + i*64, x, NTOT);
    }

    out_kernel<<<NTOT, 64>>>(emb, x, negE, out);
}

// round 4
// speedup vs baseline: 2.2576x; 2.2576x over previous
#include <cuda_runtime.h>
#include <cuda_bf16.h>
#include <math.h>

// ---------------- problem constants ----------------
#define BB   256
#define LL   201
#define DD   1536
#define HH   64
#define NHD  2
#define DH   32
#define FF   256
#define NTOT (BB*LL)          // 51456 = 201 * 256

// output offsets (float elements)
#define OFF1 0
#define OFF2 3276800
#define OFF3 6553600
#define OFF4 9830400
#define SIMO 16416768

// ---------------- scratch ----------------
__device__ float g_T1  [NTOT*HH];
__device__ float g_Tneg[NTOT*HH];
__device__ float g_emb [NTOT*HH];
__device__ float g_negE[NTOT*HH];
__device__ float g_x   [NTOT*HH];
__device__ float g_tmp [NTOT*HH];
__device__ float g_qkv [NTOT*192];
__device__ float g_attn[NTOT*HH];
__device__ float g_ff1 [NTOT*FF];
__device__ float g_xsum[BB*DD];
__device__ float g_uon [BB*HH];
__device__ float g_part[6432];

// ---------------- helpers ----------------
__device__ __forceinline__ float wsum(float v){
    #pragma unroll
    for (int o = 16; o; o >>= 1) v += __shfl_xor_sync(0xffffffffu, v, o);
    return v;
}
__device__ __forceinline__ float gelu_f(float x){
    float x3 = x*x*x;
    return 0.5f*x*(1.f + tanhf(0.7978845608028654f*(x + 0.044715f*x3)));
}

// ---------------- unified register-tiled GEMM ----------------
// out[N, MTOT] = X[N, KTOT] @ W[KTOT, MTOT] + bias (+res) (gelu?)
// block: 256 rows x 64 cols (grid.y = MTOT/64), 256 threads, 8x8 per thread.
template<int KTOT, int MTOT, bool GELU, bool RES>
__global__ void __launch_bounds__(256, 2) gemm_rt(const float* __restrict__ X,
        const float* __restrict__ W, const float* __restrict__ bias,
        const float* __restrict__ res, float* __restrict__ out)
{
    extern __shared__ float sm[];
    float* Xs = sm;              // [64][260]  k-major (k, row)
    float* Ws = sm + 64*260;     // [64][68]
    const int row0 = blockIdx.x * 256;
    const int cc   = blockIdx.y * 64;
    const int t = threadIdx.x;
    const int rg = t >> 3;      // 0..31 -> rows rg*8..rg*8+7
    const int cg = t & 7;       // 0..7  -> cols cg*8..cg*8+7

    float acc[8][8];
    #pragma unroll
    for (int i = 0; i < 8; i++)
        #pragma unroll
        for (int j = 0; j < 8; j++) acc[i][j] = 0.f;

    for (int kc = 0; kc < KTOT; kc += 64) {
        #pragma unroll
        for (int it = 0; it < 16; it++) {
            int idx = t + it*256;          // 4096 float4 = 256 rows x 16
            int c4 = idx & 15, r = idx >> 4;
            float4 v = *(const float4*)(X + (size_t)(row0 + r)*KTOT + kc + c4*4);
            Xs[(c4*4+0)*260 + r] = v.x;
            Xs[(c4*4+1)*260 + r] = v.y;
            Xs[(c4*4+2)*260 + r] = v.z;
            Xs[(c4*4+3)*260 + r] = v.w;
        }
        #pragma unroll
        for (int it = 0; it < 4; it++) {
            int idx = t + it*256;          // 1024 float4 = 64 k x 16
            int c4 = idx & 15, k = idx >> 4;
            *(float4*)(Ws + k*68 + c4*4) =
                *(const float4*)(W + (size_t)(kc + k)*MTOT + cc + c4*4);
        }
        __syncthreads();
        #pragma unroll 8
        for (int k = 0; k < 64; k++) {
            float4 a0 = *(const float4*)(Xs + k*260 + rg*8);
            float4 a1 = *(const float4*)(Xs + k*260 + rg*8 + 4);
            float4 b0 = *(const float4*)(Ws + k*68 + cg*8);
            float4 b1 = *(const float4*)(Ws + k*68 + cg*8 + 4);
            float a[8] = {a0.x,a0.y,a0.z,a0.w,a1.x,a1.y,a1.z,a1.w};
            float b[8] = {b0.x,b0.y,b0.z,b0.w,b1.x,b1.y,b1.z,b1.w};
            #pragma unroll
            for (int i = 0; i < 8; i++)
                #pragma unroll
                for (int j = 0; j < 8; j++)
                    acc[i][j] = fmaf(a[i], b[j], acc[i][j]);
        }
        __syncthreads();
    }

    float bl[8];
    #pragma unroll
    for (int j = 0; j < 8; j++) bl[j] = bias[cc + cg*8 + j];

    #pragma unroll
    for (int i = 0; i < 8; i++) {
        size_t r = (size_t)(row0 + rg*8 + i);
        float v[8];
        #pragma unroll
        for (int j = 0; j < 8; j++) v[j] = acc[i][j] + bl[j];
        if (RES) {
            float4 r0 = *(const float4*)(res + r*MTOT + cc + cg*8);
            float4 r1 = *(const float4*)(res + r*MTOT + cc + cg*8 + 4);
            v[0]+=r0.x; v[1]+=r0.y; v[2]+=r0.z; v[3]+=r0.w;
            v[4]+=r1.x; v[5]+=r1.y; v[6]+=r1.z; v[7]+=r1.w;
        }
        if (GELU) {
            #pragma unroll
            for (int j = 0; j < 8; j++) v[j] = gelu_f(v[j]);
        }
        float4 o0 = make_float4(v[0],v[1],v[2],v[3]);
        float4 o1 = make_float4(v[4],v[5],v[6],v[7]);
        *(float4*)(out + r*MTOT + cc + cg*8)     = o0;
        *(float4*)(out + r*MTOT + cc + cg*8 + 4) = o1;
    }
}

// ---------------- LayerNorm over H=64 ----------------
__global__ void ln_kernel(const float* __restrict__ in, const float* __restrict__ pos,
                          const float* __restrict__ g, const float* __restrict__ b,
                          float* __restrict__ out, int N)
{
    int row = blockIdx.x * 8 + (threadIdx.x >> 5);
    int lane = threadIdx.x & 31;
    if (row >= N) return;
    int l = row % LL;
    float v0 = in[(size_t)row*64 + lane];
    float v1 = in[(size_t)row*64 + 32 + lane];
    if (pos) { v0 += pos[l*64 + lane]; v1 += pos[l*64 + 32 + lane]; }
    float mean = wsum(v0 + v1) * (1.f/64.f);
    float d0 = v0 - mean, d1 = v1 - mean;
    float var = wsum(d0*d0 + d1*d1) * (1.f/64.f);
    float inv = rsqrtf(var + 1e-5f);
    out[(size_t)row*64 + lane]      = d0*inv*g[lane]    + b[lane];
    out[(size_t)row*64 + 32 + lane] = d1*inv*g[lane+32] + b[lane+32];
}

// ---------------- attention v2 ----------------
// one block per (b,h); 8 warps; warp handles query groups of 8 with causal skip.
// SMEM layout: float4-accessed regions (Sc, Qw, Inv) FIRST (16B alignment),
// scalar-accessed (Ks, Vs, Ms) after.
__global__ void __launch_bounds__(256) attn_kernel(const float* __restrict__ qkv,
        const int* __restrict__ mask, float* __restrict__ O)
{
    extern __shared__ float sm[];
    float* Sc  = sm;                      // 8 * 204*8   probs [j][q]  (float4)
    float* Qw  = Sc + 8*204*8;            // 8 * 32*8    q d-major [d][q] (float4)
    float* Inv = Qw + 8*256;              // 8*8
    float* Ks  = Inv + 64;                // 201*33 (scalar)
    float* Vs  = Ks + 201*33;             // 201*33 (scalar)
    float* Ms  = Vs + 201*33;             // 201

    int bh = blockIdx.x;
    int b = bh >> 1, h = bh & 1;
    const float* base = qkv + (size_t)b*LL*192;
    int t = threadIdx.x;

    for (int i = t; i < LL*32; i += 256) {
        int j = i >> 5, d = i & 31;
        Ks[j*33 + d] = base[j*192 + 64  + h*32 + d];
        Vs[j*33 + d] = base[j*192 + 128 + h*32 + d];
    }
    for (int i = t; i < LL; i += 256) Ms[i] = (float)mask[b*LL + i];
    __syncthreads();

    int w = t >> 5, lane = t & 31;
    float* sc = Sc + w*204*8;
    float* qw = Qw + w*256;
    const float scale = 0.17677669529663687f;  // 1/sqrt(32)

    for (int g = w; g < 26; g += 8) {
        int base_q = g*8;
        #pragma unroll
        for (int q = 0; q < 8; q++) {
            int lq = min(base_q + q, LL-1);
            qw[lane*8 + q] = base[(size_t)lq*192 + h*32 + lane];
        }
        __syncwarp();

        int jmax = min(LL, base_q + 8);

        auto scorepass = [&](int jhi) {
            for (int j0 = 0; j0 < jhi; j0 += 32) {
                int j = j0 + lane;
                if (j < jhi) {
                    float dot[8];
                    #pragma unroll
                    for (int q = 0; q < 8; q++) dot[q] = 0.f;
                    #pragma unroll
                    for (int d = 0; d < 32; d++) {
                        float kv = Ks[j*33 + d];
                        float4 qa = *(const float4*)(qw + d*8);
                        float4 qb = *(const float4*)(qw + d*8 + 4);
                        dot[0] = fmaf(kv, qa.x, dot[0]);
                        dot[1] = fmaf(kv, qa.y, dot[1]);
                        dot[2] = fmaf(kv, qa.z, dot[2]);
                        dot[3] = fmaf(kv, qa.w, dot[3]);
                        dot[4] = fmaf(kv, qb.x, dot[4]);
                        dot[5] = fmaf(kv, qb.y, dot[5]);
                        dot[6] = fmaf(kv, qb.z, dot[6]);
                        dot[7] = fmaf(kv, qb.w, dot[7]);
                    }
                    float m = Ms[j];
                    float s8[8];
                    #pragma unroll
                    for (int q = 0; q < 8; q++) {
                        int lq = min(base_q + q, LL-1);
                        bool allowed = (j <= lq) && (m > 0.f);
                        s8[q] = dot[q]*scale + (allowed ? 0.f : -1e9f);
                    }
                    *(float4*)(sc + j*8)     = make_float4(s8[0],s8[1],s8[2],s8[3]);
                    *(float4*)(sc + j*8 + 4) = make_float4(s8[4],s8[5],s8[6],s8[7]);
                }
            }
        };

        scorepass(jmax);
        __syncwarp();

        int qi = lane & 7, jo = lane >> 3;   // 4 lanes per query
        auto reduce_mx = [&](int jlen) {
            float mx = -INFINITY;
            for (int j = jo; j < jlen; j += 4) mx = fmaxf(mx, sc[j*8 + qi]);
            mx = fmaxf(mx, __shfl_xor_sync(0xffffffffu, mx, 8));
            mx = fmaxf(mx, __shfl_xor_sync(0xffffffffu, mx, 16));
            return mx;
        };
        float mx = reduce_mx(jmax);
        int jlen = jmax;
        if (__any_sync(0xffffffffu, mx < -1e8f)) {
            // some query has an all-masked prefix: reference softmax then spans
            // ALL 201 keys (everything at ~-1e9). Redo full range.
            jlen = LL;
            scorepass(LL);
            __syncwarp();
            mx = reduce_mx(LL);
        }

        float s = 0.f;
        for (int j = jo; j < jlen; j += 4) {
            float e = __expf(sc[j*8 + qi] - mx);
            sc[j*8 + qi] = e;
            s += e;
        }
        s += __shfl_xor_sync(0xffffffffu, s, 8);
        s += __shfl_xor_sync(0xffffffffu, s, 16);
        if (lane < 8) Inv[w*8 + lane] = 1.f / s;
        __syncwarp();

        float acc[8];
        #pragma unroll
        for (int q = 0; q < 8; q++) acc[q] = 0.f;
        for (int j = 0; j < jlen; j++) {
            float v = Vs[j*33 + lane];
            float4 pa = *(const float4*)(sc + j*8);
            float4 pb = *(const float4*)(sc + j*8 + 4);
            acc[0] = fmaf(pa.x, v, acc[0]);
            acc[1] = fmaf(pa.y, v, acc[1]);
            acc[2] = fmaf(pa.z, v, acc[2]);
            acc[3] = fmaf(pa.w, v, acc[3]);
            acc[4] = fmaf(pb.x, v, acc[4]);
            acc[5] = fmaf(pb.y, v, acc[5]);
            acc[6] = fmaf(pb.z, v, acc[6]);
            acc[7] = fmaf(pb.w, v, acc[7]);
        }
        #pragma unroll
        for (int q = 0; q < 8; q++) {
            int lq = min(base_q + q, LL-1);
            O[((size_t)b*LL + lq)*64 + h*32 + lane] = acc[q] * Inv[w*8 + q];
        }
        __syncwarp();
    }
}

// ---------------- masked sum of interaction_list over L ----------------
__global__ void xsum_kernel(const float* __restrict__ X, const int* __restrict__ mask,
                            float* __restrict__ Xsum)
{
    int b = blockIdx.x;
    int d4 = threadIdx.x;           // 384 threads * 4 = 1536
    const float* xb = X + (size_t)b*LL*DD;
    float4 acc = make_float4(0.f,0.f,0.f,0.f);
    for (int l = 0; l < LL; l++) {
        if (mask[b*LL + l]) {
            float4 v = *(const float4*)(xb + (size_t)l*DD + d4*4);
            acc.x += v.x; acc.y += v.y; acc.z += v.z; acc.w += v.w;
        }
    }
    *(float4*)(Xsum + (size_t)b*DD + d4*4) = acc;
}

// ---------------- collapsed GNN ----------------
__global__ void gnn_kernel(const float* __restrict__ Xsum, const int* __restrict__ mask,
                           const float* __restrict__ wg1, const float* __restrict__ bg1,
                           const float* __restrict__ wg2, float* __restrict__ uon)
{
    __shared__ float xs[DD];
    __shared__ float h1[FF];
    __shared__ int   Scnt;
    int b = blockIdx.x, t = threadIdx.x;
    for (int i = t; i < DD; i += 256) xs[i] = Xsum[(size_t)b*DD + i];
    int cnt = 0;
    for (int l = t; l < LL; l += 256) cnt += mask[b*LL + l];
    if (t == 0) Scnt = 0;
    __syncthreads();
    if (cnt) atomicAdd(&Scnt, cnt);
    __syncthreads();
    float S = (float)Scnt;
    float scale = S > 0.f ? 1.f/S : 0.f;
    float mg = 0.f;
    for (int k = 0; k < DD; k++) mg += xs[k] * wg1[(size_t)k*FF + t];
    h1[t] = fmaxf(mg*scale + bg1[t], 0.f);
    __syncthreads();
    if (t < 64) {
        float u = 0.f;
        for (int f = 0; f < FF; f++) u += h1[f] * wg2[(size_t)f*64 + t];
        uon[b*64 + t] = (S > 0.f) ? u : 0.f;
    }
}

// ---------------- similarity ----------------
__global__ void sim_kernel(const float* __restrict__ emb, const float* __restrict__ uon,
                           const float* __restrict__ bg2, const int* __restrict__ mask,
                           float* __restrict__ partial)
{
    __shared__ float ps[8];
    int w = threadIdx.x >> 5, lane = threadIdx.x & 31;
    int row = blockIdx.x * 8 + w;
    float c = 0.f;
    if (row < NTOT) {
        int b = row / LL;
        float m = (float)mask[row];
        float e0 = emb[(size_t)row*64 + lane];
        float e1 = emb[(size_t)row*64 + 32 + lane];
        float g0 = m*uon[b*64 + lane]      + bg2[lane];
        float g1 = m*uon[b*64 + 32 + lane] + bg2[lane+32];
        float num = wsum(e0*g0 + e1*g1);
        float na  = wsum(e0*e0 + e1*e1);
        float nb  = wsum(g0*g0 + g1*g1);
        na = fmaxf(sqrtf(na), 1e-8f);
        nb = fmaxf(sqrtf(nb), 1e-8f);
        c = num / (na*nb);
    }
    if (lane == 0) ps[w] = c;
    __syncthreads();
    if (threadIdx.x == 0) {
        float s = 0.f;
        #pragma unroll
        for (int i = 0; i < 8; i++) s += ps[i];
        partial[blockIdx.x] = s;
    }
}

__global__ void sim_reduce(const float* __restrict__ partial, float* __restrict__ out)
{
    __shared__ float smem[256];
    float s = 0.f;
    for (int i = threadIdx.x; i < 6432; i += 256) s += partial[i];
    smem[threadIdx.x] = s;
    __syncthreads();
    for (int o = 128; o; o >>= 1) {
        if (threadIdx.x < o) smem[threadIdx.x] += smem[threadIdx.x + o];
        __syncthreads();
    }
    if (threadIdx.x == 0) out[0] = smem[0] / (float)(LL*BB);
}

// ---------------- output assembly ----------------
__global__ void out_kernel(const float* __restrict__ emb, const float* __restrict__ x,
                           const float* __restrict__ negE, float* __restrict__ out)
{
    int row = blockIdx.x;
    int t = threadIdx.x;   // 64
    int b = row / LL, l = row % LL;
    float e  = emb[(size_t)row*64 + t];
    float xv = x[(size_t)row*64 + t];
    out[OFF4 + (size_t)row*128 + t]      = e;
    out[OFF4 + (size_t)row*128 + 64 + t] = xv;
    if (l < LL-1) {
        size_t r200 = (size_t)b*(LL-1) + l;
        out[OFF1 + r200*64 + t] = xv;
        out[OFF2 + r200*64 + t] = emb[((size_t)b*LL + l + 1)*64 + t];
        out[OFF3 + r200*64 + t] = negE[(size_t)row*64 + t];
    }
}

// ---------------- host ----------------
template <typename T>
static float* symaddr(T& sym){ void* p = nullptr; cudaGetSymbolAddress(&p, sym); return (float*)p; }

extern "C" void kernel_launch(void* const* d_in, const int* in_sizes, int n_in,
                              void* d_out, int out_size)
{
    const float* inter = (const float*)d_in[0];
    const float* neg   = (const float*)d_in[1];
    const float* fc_w  = (const float*)d_in[2];
    const float* fc_b  = (const float*)d_in[3];
    const float* mlp_w = (const float*)d_in[4];
    const float* mlp_b = (const float*)d_in[5];
    const float* pos   = (const float*)d_in[6];
    const float* ln0g  = (const float*)d_in[7];
    const float* ln0b  = (const float*)d_in[8];
    const float* wqkv  = (const float*)d_in[9];
    const float* bqkv  = (const float*)d_in[10];
    const float* wo    = (const float*)d_in[11];
    const float* bo    = (const float*)d_in[12];
    const float* ln1g  = (const float*)d_in[13];
    const float* ln1b  = (const float*)d_in[14];
    const float* w1    = (const float*)d_in[15];
    const float* b1    = (const float*)d_in[16];
    const float* w2    = (const float*)d_in[17];
    const float* b2    = (const float*)d_in[18];
    const float* ln2g  = (const float*)d_in[19];
    const float* ln2b  = (const float*)d_in[20];
    const float* wg1   = (const float*)d_in[21];
    const float* bg1   = (const float*)d_in[22];
    const float* wg2   = (const float*)d_in[23];
    const float* bg2   = (const float*)d_in[24];
    const int*   mask  = (const int*)d_in[25];
    float* out = (float*)d_out;

    float* T1   = symaddr(g_T1);
    float* Tneg = symaddr(g_Tneg);
    float* emb  = symaddr(g_emb);
    float* negE = symaddr(g_negE);
    float* x    = symaddr(g_x);
    float* tmp  = symaddr(g_tmp);
    float* qkvb = symaddr(g_qkv);
    float* attO = symaddr(g_attn);
    float* ff1  = symaddr(g_ff1);
    float* Xsum = symaddr(g_xsum);
    float* uon  = symaddr(g_uon);
    float* part = symaddr(g_part);

    const int SMEM_G = (64*260 + 64*68) * 4;   // 83968
    const int SMEM_A = (8*204*8 + 8*256 + 64 + 201*33*2 + 201) * 4; // 114540

    cudaFuncSetAttribute((const void*)gemm_rt<1536,64,false,false>,
                         cudaFuncAttributeMaxDynamicSharedMemorySize, SMEM_G);
    cudaFuncSetAttribute((const void*)gemm_rt<64,64,true,false>,
                         cudaFuncAttributeMaxDynamicSharedMemorySize, SMEM_G);
    cudaFuncSetAttribute((const void*)gemm_rt<64,192,false,false>,
                         cudaFuncAttributeMaxDynamicSharedMemorySize, SMEM_G);
    cudaFuncSetAttribute((const void*)gemm_rt<64,64,false,true>,
                         cudaFuncAttributeMaxDynamicSharedMemorySize, SMEM_G);
    cudaFuncSetAttribute((const void*)gemm_rt<64,256,true,false>,
                         cudaFuncAttributeMaxDynamicSharedMemorySize, SMEM_G);
    cudaFuncSetAttribute((const void*)gemm_rt<256,64,false,true>,
                         cudaFuncAttributeMaxDynamicSharedMemorySize, SMEM_G);
    cudaFuncSetAttribute((const void*)attn_kernel,
                         cudaFuncAttributeMaxDynamicSharedMemorySize, SMEM_A);

    const int GR = NTOT/256;   // 201
    const int GL = NTOT/8;     // 6432

    // embedding towers
    gemm_rt<1536,64,false,false><<<dim3(GR,1), 256, SMEM_G>>>(inter, fc_w, fc_b, nullptr, T1);
    gemm_rt<1536,64,false,false><<<dim3(GR,1), 256, SMEM_G>>>(neg,   fc_w, fc_b, nullptr, Tneg);
    gemm_rt<64,64,true,false><<<dim3(GR,1), 256, SMEM_G>>>(T1,   mlp_w, mlp_b, nullptr, emb);
    gemm_rt<64,64,true,false><<<dim3(GR,1), 256, SMEM_G>>>(Tneg, mlp_w, mlp_b, nullptr, negE);

    // collapsed GNN + similarity
    xsum_kernel<<<BB, 384>>>(inter, mask, Xsum);
    gnn_kernel<<<BB, 256>>>(Xsum, mask, wg1, bg1, wg2, uon);
    sim_kernel<<<GL, 256>>>(emb, uon, bg2, mask, part);
    sim_reduce<<<1, 256>>>(part, out + SIMO);

    // encoder
    ln_kernel<<<GL, 256>>>(emb, pos, ln0g, ln0b, x, NTOT);
    for (int i = 0; i < 2; i++) {
        gemm_rt<64,192,false,false><<<dim3(GR,3), 256, SMEM_G>>>(x, wqkv + (size_t)i*64*192,
                                                                 bqkv + i*192, nullptr, qkvb);
        attn_kernel<<<BB*NHD, 256, SMEM_A>>>(qkvb, mask, attO);
        gemm_rt<64,64,false,true><<<dim3(GR,1), 256, SMEM_G>>>(attO, wo + (size_t)i*64*64,
                                                               bo + i*64, x, tmp);
        ln_kernel<<<GL, 256>>>(tmp, nullptr, ln1g + i*64, ln1b + i*64, x, NTOT);
        gemm_rt<64,256,true,false><<<dim3(GR,4), 256, SMEM_G>>>(x, w1 + (size_t)i*64*256,
                                                                b1 + i*256, nullptr, ff1);
        gemm_rt<256,64,false,true><<<dim3(GR,1), 256, SMEM_G>>>(ff1, w2 + (size_t)i*256*64,
                                                                b2 + i*64, x, tmp);
        ln_kernel<<<GL, 256>>>(tmp, nullptr, ln2g + i*64, ln2b + i*64, x, NTOT);
    }

    out_kernel<<<NTOT, 64>>>(emb, x, negE, out);
}

// round 8
// speedup vs baseline: 3.1962x; 1.4157x over previous
#include <cuda_runtime.h>
#include <cuda_bf16.h>
#include <mma.h>
#include <math.h>
#include <stdint.h>

using namespace nvcuda;

// ---------------- problem constants ----------------
#define BB   256
#define LL   201
#define DD   1536
#define HH   64
#define NHD  2
#define DH   32
#define FF   256
#define NTOT (BB*LL)          // 51456 = 128 * 402

// output offsets (float elements)
#define OFF1 0
#define OFF2 3276800
#define OFF3 6553600
#define OFF4 9830400
#define SIMO 16416768

// ---------------- scratch ----------------
__device__ float g_T1  [NTOT*HH];
__device__ float g_Tneg[NTOT*HH];
__device__ float g_emb [NTOT*HH];
__device__ float g_negE[NTOT*HH];
__device__ float g_x   [NTOT*HH];
__device__ float g_tmp [NTOT*HH];
__device__ float g_qkv [NTOT*192];
__device__ float g_attn[NTOT*HH];
__device__ float g_ff1 [NTOT*FF];
__device__ float g_xsum[BB*DD];
__device__ float g_uon [BB*HH];
__device__ float g_part[6432];
__device__ __nv_bfloat16 g_WtHi[1536*64];   // [k][n], same layout as fc_w
__device__ __nv_bfloat16 g_WtLo[1536*64];

// ---------------- helpers ----------------
__device__ __forceinline__ float wsum(float v){
    #pragma unroll
    for (int o = 16; o; o >>= 1) v += __shfl_xor_sync(0xffffffffu, v, o);
    return v;
}
__device__ __forceinline__ float gelu_f(float x){
    float x3 = x*x*x;
    return 0.5f*x*(1.f + tanhf(0.7978845608028654f*(x + 0.044715f*x3)));
}

// ---------------- W prep: fc_w [1536][64] fp32 -> hi/lo bf16 (same layout) ----------------
__global__ void wconv_kernel(const float* __restrict__ W,
                             __nv_bfloat16* __restrict__ Hi, __nv_bfloat16* __restrict__ Lo)
{
    int idx = blockIdx.x*256 + threadIdx.x;     // 98304
    float w = W[idx];
    __nv_bfloat16 h = __float2bfloat16(w);
    Hi[idx] = h;
    Lo[idx] = __float2bfloat16(w - __bfloat162float(h));
}

// ---------------- tensor-core tower GEMM via wmma (bf16x3, fp32 accum) ----------------
// out[N, 64] = X[N, KTOT] @ W[KTOT, 64] + bias.  CTA: 128 rows; 8 warps 4x2.
// smem: Ahi[128][72], Alo[128][72], Bhi[64][72], Blo[64][72] bf16; C reuses region.
template<int KTOT>
__global__ void __launch_bounds__(256, 2) gemm_wmma(const float* __restrict__ X,
        const __nv_bfloat16* __restrict__ WHi, const __nv_bfloat16* __restrict__ WLo,
        const float* __restrict__ bias, float* __restrict__ out)
{
    extern __shared__ char smw[];
    __nv_bfloat16* Ahi = (__nv_bfloat16*)smw;       // 128*72
    __nv_bfloat16* Alo = Ahi + 128*72;
    __nv_bfloat16* Bhi = Alo + 128*72;              // 64*72
    __nv_bfloat16* Blo = Bhi + 64*72;
    float* Cs = (float*)smw;                        // reuse: 8 warps * 32*36 floats

    const int t = threadIdx.x;
    const int w = t >> 5, lane = t & 31;
    const int wm = w >> 1, wn = w & 1;
    const size_t row0 = (size_t)blockIdx.x * 128;

    wmma::fragment<wmma::accumulator,16,16,16,float> acc[2][2];
    #pragma unroll
    for (int mi = 0; mi < 2; mi++)
        #pragma unroll
        for (int ni = 0; ni < 2; ni++) wmma::fill_fragment(acc[mi][ni], 0.f);

    for (int kc = 0; kc < KTOT; kc += 64) {
        // A: 128x64 fp32 -> bf16 hi/lo
        #pragma unroll
        for (int it = 0; it < 8; it++) {
            int idx = t + it*256;           // 0..2047 float4
            int r = idx >> 4, c4 = idx & 15;
            float4 v = *(const float4*)(X + (row0 + r)*KTOT + kc + c4*4);
            __nv_bfloat162 h0 = __float22bfloat162_rn(make_float2(v.x, v.y));
            __nv_bfloat162 h1 = __float22bfloat162_rn(make_float2(v.z, v.w));
            float2 f0 = __bfloat1622float2(h0);
            float2 f1 = __bfloat1622float2(h1);
            __nv_bfloat162 l0 = __float22bfloat162_rn(make_float2(v.x - f0.x, v.y - f0.y));
            __nv_bfloat162 l1 = __float22bfloat162_rn(make_float2(v.z - f1.x, v.w - f1.y));
            uint2 hv, lv;
            hv.x = *reinterpret_cast<uint32_t*>(&h0);
            hv.y = *reinterpret_cast<uint32_t*>(&h1);
            lv.x = *reinterpret_cast<uint32_t*>(&l0);
            lv.y = *reinterpret_cast<uint32_t*>(&l1);
            *(uint2*)(Ahi + r*72 + c4*4) = hv;
            *(uint2*)(Alo + r*72 + c4*4) = lv;
        }
        // B: 64x64 bf16 rows kc..kc+63 (already split)
        #pragma unroll
        for (int it = 0; it < 2; it++) {
            int idx = t + it*256;           // 0..511, 8 bf16 each
            int r = idx >> 3, c8 = idx & 7;
            uint4 vh = *(const uint4*)(WHi + (size_t)(kc + r)*64 + c8*8);
            uint4 vl = *(const uint4*)(WLo + (size_t)(kc + r)*64 + c8*8);
            *(uint4*)(Bhi + r*72 + c8*8) = vh;
            *(uint4*)(Blo + r*72 + c8*8) = vl;
        }
        __syncthreads();

        #pragma unroll
        for (int ks = 0; ks < 4; ks++) {
            wmma::fragment<wmma::matrix_a,16,16,16,__nv_bfloat16,wmma::row_major> ah[2], al[2];
            wmma::fragment<wmma::matrix_b,16,16,16,__nv_bfloat16,wmma::row_major> bh[2], bl[2];
            #pragma unroll
            for (int mi = 0; mi < 2; mi++) {
                wmma::load_matrix_sync(ah[mi], Ahi + (wm*32 + mi*16)*72 + ks*16, 72);
                wmma::load_matrix_sync(al[mi], Alo + (wm*32 + mi*16)*72 + ks*16, 72);
            }
            #pragma unroll
            for (int ni = 0; ni < 2; ni++) {
                wmma::load_matrix_sync(bh[ni], Bhi + (ks*16)*72 + wn*32 + ni*16, 72);
                wmma::load_matrix_sync(bl[ni], Blo + (ks*16)*72 + wn*32 + ni*16, 72);
            }
            #pragma unroll
            for (int mi = 0; mi < 2; mi++)
                #pragma unroll
                for (int ni = 0; ni < 2; ni++) {
                    wmma::mma_sync(acc[mi][ni], ah[mi], bh[ni], acc[mi][ni]);
                    wmma::mma_sync(acc[mi][ni], ah[mi], bl[ni], acc[mi][ni]);
                    wmma::mma_sync(acc[mi][ni], al[mi], bh[ni], acc[mi][ni]);
                }
        }
        __syncthreads();
    }

    // epilogue: frags -> smem (per-warp) -> bias add -> gmem
    float* Cw = Cs + w*(32*36);
    #pragma unroll
    for (int mi = 0; mi < 2; mi++)
        #pragma unroll
        for (int ni = 0; ni < 2; ni++)
            wmma::store_matrix_sync(Cw + mi*16*36 + ni*16, acc[mi][ni], 36, wmma::mem_row_major);
    __syncwarp();

    size_t gr = row0 + wm*32 + lane;
    #pragma unroll
    for (int c4 = 0; c4 < 8; c4++) {
        float4 o;
        o.x = Cw[lane*36 + c4*4+0] + __ldg(bias + wn*32 + c4*4+0);
        o.y = Cw[lane*36 + c4*4+1] + __ldg(bias + wn*32 + c4*4+1);
        o.z = Cw[lane*36 + c4*4+2] + __ldg(bias + wn*32 + c4*4+2);
        o.w = Cw[lane*36 + c4*4+3] + __ldg(bias + wn*32 + c4*4+3);
        *(float4*)(out + gr*64 + wn*32 + c4*4) = o;
    }
}

// ---------------- register-tiled GEMM (for all other matmuls) ----------------
template<int KTOT, int MTOT, bool GELU, bool RES>
__global__ void __launch_bounds__(256, 2) gemm_rt(const float* __restrict__ X,
        const float* __restrict__ W, const float* __restrict__ bias,
        const float* __restrict__ res, float* __restrict__ out)
{
    extern __shared__ float sm[];
    float* Xs = sm;              // [64][260]  k-major (k, row)
    float* Ws = sm + 64*260;     // [64][68]
    const int row0 = blockIdx.x * 256;
    const int cc   = blockIdx.y * 64;
    const int t = threadIdx.x;
    const int rg = t >> 3;
    const int cg = t & 7;

    float acc[8][8];
    #pragma unroll
    for (int i = 0; i < 8; i++)
        #pragma unroll
        for (int j = 0; j < 8; j++) acc[i][j] = 0.f;

    for (int kc = 0; kc < KTOT; kc += 64) {
        #pragma unroll
        for (int it = 0; it < 16; it++) {
            int idx = t + it*256;
            int c4 = idx & 15, r = idx >> 4;
            float4 v = *(const float4*)(X + (size_t)(row0 + r)*KTOT + kc + c4*4);
            Xs[(c4*4+0)*260 + r] = v.x;
            Xs[(c4*4+1)*260 + r] = v.y;
            Xs[(c4*4+2)*260 + r] = v.z;
            Xs[(c4*4+3)*260 + r] = v.w;
        }
        #pragma unroll
        for (int it = 0; it < 4; it++) {
            int idx = t + it*256;
            int c4 = idx & 15, k = idx >> 4;
            *(float4*)(Ws + k*68 + c4*4) =
                *(const float4*)(W + (size_t)(kc + k)*MTOT + cc + c4*4);
        }
        __syncthreads();
        #pragma unroll 8
        for (int k = 0; k < 64; k++) {
            float4 a0 = *(const float4*)(Xs + k*260 + rg*8);
            float4 a1 = *(const float4*)(Xs + k*260 + rg*8 + 4);
            float4 b0 = *(const float4*)(Ws + k*68 + cg*8);
            float4 b1 = *(const float4*)(Ws + k*68 + cg*8 + 4);
            float a[8] = {a0.x,a0.y,a0.z,a0.w,a1.x,a1.y,a1.z,a1.w};
            float b[8] = {b0.x,b0.y,b0.z,b0.w,b1.x,b1.y,b1.z,b1.w};
            #pragma unroll
            for (int i = 0; i < 8; i++)
                #pragma unroll
                for (int j = 0; j < 8; j++)
                    acc[i][j] = fmaf(a[i], b[j], acc[i][j]);
        }
        __syncthreads();
    }

    float bl[8];
    #pragma unroll
    for (int j = 0; j < 8; j++) bl[j] = bias[cc + cg*8 + j];

    #pragma unroll
    for (int i = 0; i < 8; i++) {
        size_t r = (size_t)(row0 + rg*8 + i);
        float v[8];
        #pragma unroll
        for (int j = 0; j < 8; j++) v[j] = acc[i][j] + bl[j];
        if (RES) {
            float4 r0 = *(const float4*)(res + r*MTOT + cc + cg*8);
            float4 r1 = *(const float4*)(res + r*MTOT + cc + cg*8 + 4);
            v[0]+=r0.x; v[1]+=r0.y; v[2]+=r0.z; v[3]+=r0.w;
            v[4]+=r1.x; v[5]+=r1.y; v[6]+=r1.z; v[7]+=r1.w;
        }
        if (GELU) {
            #pragma unroll
            for (int j = 0; j < 8; j++) v[j] = gelu_f(v[j]);
        }
        *(float4*)(out + r*MTOT + cc + cg*8)     = make_float4(v[0],v[1],v[2],v[3]);
        *(float4*)(out + r*MTOT + cc + cg*8 + 4) = make_float4(v[4],v[5],v[6],v[7]);
    }
}

// ---------------- LayerNorm over H=64 ----------------
__global__ void ln_kernel(const float* __restrict__ in, const float* __restrict__ pos,
                          const float* __restrict__ g, const float* __restrict__ b,
                          float* __restrict__ out, int N)
{
    int row = blockIdx.x * 8 + (threadIdx.x >> 5);
    int lane = threadIdx.x & 31;
    if (row >= N) return;
    int l = row % LL;
    float v0 = in[(size_t)row*64 + lane];
    float v1 = in[(size_t)row*64 + 32 + lane];
    if (pos) { v0 += pos[l*64 + lane]; v1 += pos[l*64 + 32 + lane]; }
    float mean = wsum(v0 + v1) * (1.f/64.f);
    float d0 = v0 - mean, d1 = v1 - mean;
    float var = wsum(d0*d0 + d1*d1) * (1.f/64.f);
    float inv = rsqrtf(var + 1e-5f);
    out[(size_t)row*64 + lane]      = d0*inv*g[lane]    + b[lane];
    out[(size_t)row*64 + 32 + lane] = d1*inv*g[lane+32] + b[lane+32];
}

// ---------------- attention (unchanged from R4) ----------------
__global__ void __launch_bounds__(256) attn_kernel(const float* __restrict__ qkv,
        const int* __restrict__ mask, float* __restrict__ O)
{
    extern __shared__ float sm[];
    float* Sc  = sm;                      // 8 * 204*8
    float* Qw  = Sc + 8*204*8;            // 8 * 256
    float* Inv = Qw + 8*256;              // 64
    float* Ks  = Inv + 64;                // 201*33
    float* Vs  = Ks + 201*33;             // 201*33
    float* Ms  = Vs + 201*33;             // 201

    int bh = blockIdx.x;
    int b = bh >> 1, h = bh & 1;
    const float* base = qkv + (size_t)b*LL*192;
    int t = threadIdx.x;

    for (int i = t; i < LL*32; i += 256) {
        int j = i >> 5, d = i & 31;
        Ks[j*33 + d] = base[j*192 + 64  + h*32 + d];
        Vs[j*33 + d] = base[j*192 + 128 + h*32 + d];
    }
    for (int i = t; i < LL; i += 256) Ms[i] = (float)mask[b*LL + i];
    __syncthreads();

    int w = t >> 5, lane = t & 31;
    float* sc = Sc + w*204*8;
    float* qw = Qw + w*256;
    const float scale = 0.17677669529663687f;

    for (int g = w; g < 26; g += 8) {
        int base_q = g*8;
        #pragma unroll
        for (int q = 0; q < 8; q++) {
            int lq = min(base_q + q, LL-1);
            qw[lane*8 + q] = base[(size_t)lq*192 + h*32 + lane];
        }
        __syncwarp();

        int jmax = min(LL, base_q + 8);

        auto scorepass = [&](int jhi) {
            for (int j0 = 0; j0 < jhi; j0 += 32) {
                int j = j0 + lane;
                if (j < jhi) {
                    float dot[8];
                    #pragma unroll
                    for (int q = 0; q < 8; q++) dot[q] = 0.f;
                    #pragma unroll
                    for (int d = 0; d < 32; d++) {
                        float kv = Ks[j*33 + d];
                        float4 qa = *(const float4*)(qw + d*8);
                        float4 qb = *(const float4*)(qw + d*8 + 4);
                        dot[0] = fmaf(kv, qa.x, dot[0]);
                        dot[1] = fmaf(kv, qa.y, dot[1]);
                        dot[2] = fmaf(kv, qa.z, dot[2]);
                        dot[3] = fmaf(kv, qa.w, dot[3]);
                        dot[4] = fmaf(kv, qb.x, dot[4]);
                        dot[5] = fmaf(kv, qb.y, dot[5]);
                        dot[6] = fmaf(kv, qb.z, dot[6]);
                        dot[7] = fmaf(kv, qb.w, dot[7]);
                    }
                    float m = Ms[j];
                    float s8[8];
                    #pragma unroll
                    for (int q = 0; q < 8; q++) {
                        int lq = min(base_q + q, LL-1);
                        bool allowed = (j <= lq) && (m > 0.f);
                        s8[q] = dot[q]*scale + (allowed ? 0.f : -1e9f);
                    }
                    *(float4*)(sc + j*8)     = make_float4(s8[0],s8[1],s8[2],s8[3]);
                    *(float4*)(sc + j*8 + 4) = make_float4(s8[4],s8[5],s8[6],s8[7]);
                }
            }
        };

        scorepass(jmax);
        __syncwarp();

        int qi = lane & 7, jo = lane >> 3;
        auto reduce_mx = [&](int jlen) {
            float mx = -INFINITY;
            for (int j = jo; j < jlen; j += 4) mx = fmaxf(mx, sc[j*8 + qi]);
            mx = fmaxf(mx, __shfl_xor_sync(0xffffffffu, mx, 8));
            mx = fmaxf(mx, __shfl_xor_sync(0xffffffffu, mx, 16));
            return mx;
        };
        float mx = reduce_mx(jmax);
        int jlen = jmax;
        if (__any_sync(0xffffffffu, mx < -1e8f)) {
            jlen = LL;
            scorepass(LL);
            __syncwarp();
            mx = reduce_mx(LL);
        }

        float s = 0.f;
        for (int j = jo; j < jlen; j += 4) {
            float e = __expf(sc[j*8 + qi] - mx);
            sc[j*8 + qi] = e;
            s += e;
        }
        s += __shfl_xor_sync(0xffffffffu, s, 8);
        s += __shfl_xor_sync(0xffffffffu, s, 16);
        if (lane < 8) Inv[w*8 + lane] = 1.f / s;
        __syncwarp();

        float acc[8];
        #pragma unroll
        for (int q = 0; q < 8; q++) acc[q] = 0.f;
        for (int j = 0; j < jlen; j++) {
            float v = Vs[j*33 + lane];
            float4 pa = *(const float4*)(sc + j*8);
            float4 pb = *(const float4*)(sc + j*8 + 4);
            acc[0] = fmaf(pa.x, v, acc[0]);
            acc[1] = fmaf(pa.y, v, acc[1]);
            acc[2] = fmaf(pa.z, v, acc[2]);
            acc[3] = fmaf(pa.w, v, acc[3]);
            acc[4] = fmaf(pb.x, v, acc[4]);
            acc[5] = fmaf(pb.y, v, acc[5]);
            acc[6] = fmaf(pb.z, v, acc[6]);
            acc[7] = fmaf(pb.w, v, acc[7]);
        }
        #pragma unroll
        for (int q = 0; q < 8; q++) {
            int lq = min(base_q + q, LL-1);
            O[((size_t)b*LL + lq)*64 + h*32 + lane] = acc[q] * Inv[w*8 + q];
        }
        __syncwarp();
    }
}

// ---------------- masked sum of interaction_list over L ----------------
__global__ void xsum_kernel(const float* __restrict__ X, const int* __restrict__ mask,
                            float* __restrict__ Xsum)
{
    int b = blockIdx.x;
    int d4 = threadIdx.x;
    const float* xb = X + (size_t)b*LL*DD;
    float4 acc = make_float4(0.f,0.f,0.f,0.f);
    for (int l = 0; l < LL; l++) {
        if (mask[b*LL + l]) {
            float4 v = *(const float4*)(xb + (size_t)l*DD + d4*4);
            acc.x += v.x; acc.y += v.y; acc.z += v.z; acc.w += v.w;
        }
    }
    *(float4*)(Xsum + (size_t)b*DD + d4*4) = acc;
}

// ---------------- collapsed GNN ----------------
__global__ void gnn_kernel(const float* __restrict__ Xsum, const int* __restrict__ mask,
                           const float* __restrict__ wg1, const float* __restrict__ bg1,
                           const float* __restrict__ wg2, float* __restrict__ uon)
{
    __shared__ float xs[DD];
    __shared__ float h1[FF];
    __shared__ int   Scnt;
    int b = blockIdx.x, t = threadIdx.x;
    for (int i = t; i < DD; i += 256) xs[i] = Xsum[(size_t)b*DD + i];
    int cnt = 0;
    for (int l = t; l < LL; l += 256) cnt += mask[b*LL + l];
    if (t == 0) Scnt = 0;
    __syncthreads();
    if (cnt) atomicAdd(&Scnt, cnt);
    __syncthreads();
    float S = (float)Scnt;
    float scale = S > 0.f ? 1.f/S : 0.f;
    float mg = 0.f;
    for (int k = 0; k < DD; k++) mg += xs[k] * wg1[(size_t)k*FF + t];
    h1[t] = fmaxf(mg*scale + bg1[t], 0.f);
    __syncthreads();
    if (t < 64) {
        float u = 0.f;
        for (int f = 0; f < FF; f++) u += h1[f] * wg2[(size_t)f*64 + t];
        uon[b*64 + t] = (S > 0.f) ? u : 0.f;
    }
}

// ---------------- similarity ----------------
__global__ void sim_kernel(const float* __restrict__ emb, const float* __restrict__ uon,
                           const float* __restrict__ bg2, const int* __restrict__ mask,
                           float* __restrict__ partial)
{
    __shared__ float ps[8];
    int w = threadIdx.x >> 5, lane = threadIdx.x & 31;
    int row = blockIdx.x * 8 + w;
    float c = 0.f;
    if (row < NTOT) {
        int b = row / LL;
        float m = (float)mask[row];
        float e0 = emb[(size_t)row*64 + lane];
        float e1 = emb[(size_t)row*64 + 32 + lane];
        float g0 = m*uon[b*64 + lane]      + bg2[lane];
        float g1 = m*uon[b*64 + 32 + lane] + bg2[lane+32];
        float num = wsum(e0*g0 + e1*g1);
        float na  = wsum(e0*e0 + e1*e1);
        float nb  = wsum(g0*g0 + g1*g1);
        na = fmaxf(sqrtf(na), 1e-8f);
        nb = fmaxf(sqrtf(nb), 1e-8f);
        c = num / (na*nb);
    }
    if (lane == 0) ps[w] = c;
    __syncthreads();
    if (threadIdx.x == 0) {
        float s = 0.f;
        #pragma unroll
        for (int i = 0; i < 8; i++) s += ps[i];
        partial[blockIdx.x] = s;
    }
}

__global__ void sim_reduce(const float* __restrict__ partial, float* __restrict__ out)
{
    __shared__ float smem[256];
    float s = 0.f;
    for (int i = threadIdx.x; i < 6432; i += 256) s += partial[i];
    smem[threadIdx.x] = s;
    __syncthreads();
    for (int o = 128; o; o >>= 1) {
        if (threadIdx.x < o) smem[threadIdx.x] += smem[threadIdx.x + o];
        __syncthreads();
    }
    if (threadIdx.x == 0) out[0] = smem[0] / (float)(LL*BB);
}

// ---------------- output assembly ----------------
__global__ void out_kernel(const float* __restrict__ emb, const float* __restrict__ x,
                           const float* __restrict__ negE, float* __restrict__ out)
{
    int row = blockIdx.x;
    int t = threadIdx.x;   // 64
    int b = row / LL, l = row % LL;
    float e  = emb[(size_t)row*64 + t];
    float xv = x[(size_t)row*64 + t];
    out[OFF4 + (size_t)row*128 + t]      = e;
    out[OFF4 + (size_t)row*128 + 64 + t] = xv;
    if (l < LL-1) {
        size_t r200 = (size_t)b*(LL-1) + l;
        out[OFF1 + r200*64 + t] = xv;
        out[OFF2 + r200*64 + t] = emb[((size_t)b*LL + l + 1)*64 + t];
        out[OFF3 + r200*64 + t] = negE[(size_t)row*64 + t];
    }
}

// ---------------- host ----------------
template <typename T>
static void* symaddr_v(T& sym){ void* p = nullptr; cudaGetSymbolAddress(&p, sym); return p; }

extern "C" void kernel_launch(void* const* d_in, const int* in_sizes, int n_in,
                              void* d_out, int out_size)
{
    const float* inter = (const float*)d_in[0];
    const float* neg   = (const float*)d_in[1];
    const float* fc_w  = (const float*)d_in[2];
    const float* fc_b  = (const float*)d_in[3];
    const float* mlp_w = (const float*)d_in[4];
    const float* mlp_b = (const float*)d_in[5];
    const float* pos   = (const float*)d_in[6];
    const float* ln0g  = (const float*)d_in[7];
    const float* ln0b  = (const float*)d_in[8];
    const float* wqkv  = (const float*)d_in[9];
    const float* bqkv  = (const float*)d_in[10];
    const float* wo    = (const float*)d_in[11];
    const float* bo    = (const float*)d_in[12];
    const float* ln1g  = (const float*)d_in[13];
    const float* ln1b  = (const float*)d_in[14];
    const float* w1    = (const float*)d_in[15];
    const float* b1    = (const float*)d_in[16];
    const float* w2    = (const float*)d_in[17];
    const float* b2    = (const float*)d_in[18];
    const float* ln2g  = (const float*)d_in[19];
    const float* ln2b  = (const float*)d_in[20];
    const float* wg1   = (const float*)d_in[21];
    const float* bg1   = (const float*)d_in[22];
    const float* wg2   = (const float*)d_in[23];
    const float* bg2   = (const float*)d_in[24];
    const int*   mask  = (const int*)d_in[25];
    float* out = (float*)d_out;

    float* T1   = (float*)symaddr_v(g_T1);
    float* Tneg = (float*)symaddr_v(g_Tneg);
    float* emb  = (float*)symaddr_v(g_emb);
    float* negE = (float*)symaddr_v(g_negE);
    float* x    = (float*)symaddr_v(g_x);
    float* tmp  = (float*)symaddr_v(g_tmp);
    float* qkvb = (float*)symaddr_v(g_qkv);
    float* attO = (float*)symaddr_v(g_attn);
    float* ff1  = (float*)symaddr_v(g_ff1);
    float* Xsum = (float*)symaddr_v(g_xsum);
    float* uon  = (float*)symaddr_v(g_uon);
    float* part = (float*)symaddr_v(g_part);
    __nv_bfloat16* WtHi = (__nv_bfloat16*)symaddr_v(g_WtHi);
    __nv_bfloat16* WtLo = (__nv_bfloat16*)symaddr_v(g_WtLo);

    const int SMEM_G = (64*260 + 64*68) * 4;   // 83968
    const int SMEM_A = (8*204*8 + 8*256 + 64 + 201*33*2 + 201) * 4; // 114540
    const int SMEM_W = (2*128*72 + 2*64*72) * 2;  // 55296

    cudaFuncSetAttribute((const void*)gemm_wmma<1536>,
                         cudaFuncAttributeMaxDynamicSharedMemorySize, SMEM_W);
    cudaFuncSetAttribute((const void*)gemm_rt<64,64,true,false>,
                         cudaFuncAttributeMaxDynamicSharedMemorySize, SMEM_G);
    cudaFuncSetAttribute((const void*)gemm_rt<64,192,false,false>,
                         cudaFuncAttributeMaxDynamicSharedMemorySize, SMEM_G);
    cudaFuncSetAttribute((const void*)gemm_rt<64,64,false,true>,
                         cudaFuncAttributeMaxDynamicSharedMemorySize, SMEM_G);
    cudaFuncSetAttribute((const void*)gemm_rt<64,256,true,false>,
                         cudaFuncAttributeMaxDynamicSharedMemorySize, SMEM_G);
    cudaFuncSetAttribute((const void*)gemm_rt<256,64,false,true>,
                         cudaFuncAttributeMaxDynamicSharedMemorySize, SMEM_G);
    cudaFuncSetAttribute((const void*)attn_kernel,
                         cudaFuncAttributeMaxDynamicSharedMemorySize, SMEM_A);

    const int GR = NTOT/256;   // 201
    const int GT = NTOT/128;   // 402
    const int GL = NTOT/8;     // 6432

    // embedding towers (wmma bf16x3)
    wconv_kernel<<<384, 256>>>(fc_w, WtHi, WtLo);
    gemm_wmma<1536><<<GT, 256, SMEM_W>>>(inter, WtHi, WtLo, fc_b, T1);
    gemm_wmma<1536><<<GT, 256, SMEM_W>>>(neg,   WtHi, WtLo, fc_b, Tneg);
    gemm_rt<64,64,true,false><<<dim3(GR,1), 256, SMEM_G>>>(T1,   mlp_w, mlp_b, nullptr, emb);
    gemm_rt<64,64,true,false><<<dim3(GR,1), 256, SMEM_G>>>(Tneg, mlp_w, mlp_b, nullptr, negE);

    // collapsed GNN + similarity
    xsum_kernel<<<BB, 384>>>(inter, mask, Xsum);
    gnn_kernel<<<BB, 256>>>(Xsum, mask, wg1, bg1, wg2, uon);
    sim_kernel<<<GL, 256>>>(emb, uon, bg2, mask, part);
    sim_reduce<<<1, 256>>>(part, out + SIMO);

    // encoder
    ln_kernel<<<GL, 256>>>(emb, pos, ln0g, ln0b, x, NTOT);
    for (int i = 0; i < 2; i++) {
        gemm_rt<64,192,false,false><<<dim3(GR,3), 256, SMEM_G>>>(x, wqkv + (size_t)i*64*192,
                                                                 bqkv + i*192, nullptr, qkvb);
        attn_kernel<<<BB*NHD, 256, SMEM_A>>>(qkvb, mask, attO);
        gemm_rt<64,64,false,true><<<dim3(GR,1), 256, SMEM_G>>>(attO, wo + (size_t)i*64*64,
                                                               bo + i*64, x, tmp);
        ln_kernel<<<GL, 256>>>(tmp, nullptr, ln1g + i*64, ln1b + i*64, x, NTOT);
        gemm_rt<64,256,true,false><<<dim3(GR,4), 256, SMEM_G>>>(x, w1 + (size_t)i*64*256,
                                                                b1 + i*256, nullptr, ff1);
        gemm_rt<256,64,false,true><<<dim3(GR,1), 256, SMEM_G>>>(ff1, w2 + (size_t)i*256*64,
                                                                b2 + i*64, x, tmp);
        ln_kernel<<<GL, 256>>>(tmp, nullptr, ln2g + i*64, ln2b + i*64, x, NTOT);
    }

    out_kernel<<<NTOT, 64>>>(emb, x, negE, out);
}

// round 9
// speedup vs baseline: 3.6418x; 1.1394x over previous
#include <cuda_runtime.h>
#include <cuda_bf16.h>
#include <mma.h>
#include <math.h>
#include <stdint.h>

using namespace nvcuda;

// ---------------- problem constants ----------------
#define BB   256
#define LL   201
#define DD   1536
#define HH   64
#define NHD  2
#define DH   32
#define FF   256
#define NTOT (BB*LL)          // 51456 = 128 * 402

// output offsets (float elements)
#define OFF1 0
#define OFF2 3276800
#define OFF3 6553600
#define OFF4 9830400
#define SIMO 16416768

// weight scratch offsets (elements)
#define OFC   0
#define OMLP  98304
#define OQKV  102400
#define OWO   126976
#define OW1   135168
#define OW2   167936
#define WTOT  200704

// ---------------- scratch ----------------
__device__ float g_T1  [NTOT*HH];
__device__ float g_Tneg[NTOT*HH];
__device__ float g_emb [NTOT*HH];
__device__ float g_negE[NTOT*HH];
__device__ float g_x   [NTOT*HH];
__device__ float g_qkv [NTOT*192];
__device__ float g_attn[NTOT*HH];
__device__ float g_ff1 [NTOT*FF];
__device__ float g_xsum[BB*DD];
__device__ float g_uon [BB*HH];
__device__ float g_part[6432];
__device__ __nv_bfloat16 g_WHi[WTOT];
__device__ __nv_bfloat16 g_WLo[WTOT];

// ---------------- helpers ----------------
__device__ __forceinline__ float wsum(float v){
    #pragma unroll
    for (int o = 16; o; o >>= 1) v += __shfl_xor_sync(0xffffffffu, v, o);
    return v;
}
__device__ __forceinline__ float gelu_f(float x){
    float x3 = x*x*x;
    return 0.5f*x*(1.f + tanhf(0.7978845608028654f*(x + 0.044715f*x3)));
}

// ---------------- W prep: fp32 [k][n] -> hi/lo bf16 (same layout) ----------------
__global__ void wconv_kernel(const float* __restrict__ W,
                             __nv_bfloat16* __restrict__ Hi, __nv_bfloat16* __restrict__ Lo,
                             int n)
{
    int idx = blockIdx.x*256 + threadIdx.x;
    if (idx >= n) return;
    float w = W[idx];
    __nv_bfloat16 h = __float2bfloat16(w);
    Hi[idx] = h;
    Lo[idx] = __float2bfloat16(w - __bfloat162float(h));
}

// ---------------- unified wmma GEMM (bf16x3, fp32 accum) ----------------
// out[N, MTOT] = X[N, KTOT] @ W[KTOT, MTOT] + bias, with fused epilogues.
// EPI: 0 = bias only
//      1 = gelu(bias+..)
//      2 = out = LN(res + gemm + bias; gma, bta)      (MTOT must be 64)
//      3 = out = gelu(gemm+bias); out2 = LN(out + pos) (MTOT must be 64)
// CTA: 128 rows x 64 cols (grid.y = MTOT/64), 8 warps in 4x2.
template<int KTOT, int MTOT, int EPI>
__global__ void __launch_bounds__(256, 2) gemm_w(const float* __restrict__ X,
        const __nv_bfloat16* __restrict__ WHi, const __nv_bfloat16* __restrict__ WLo,
        const float* __restrict__ bias, const float* __restrict__ res,
        const float* __restrict__ gma, const float* __restrict__ bta,
        const float* __restrict__ pos,
        float* __restrict__ out, float* __restrict__ out2)
{
    extern __shared__ char smw[];
    __nv_bfloat16* Ahi = (__nv_bfloat16*)smw;       // 128*72
    __nv_bfloat16* Alo = Ahi + 128*72;
    __nv_bfloat16* Bhi = Alo + 128*72;              // 64*72
    __nv_bfloat16* Blo = Bhi + 64*72;

    const int t = threadIdx.x;
    const int w = t >> 5, lane = t & 31;
    const int wm = w >> 1, wn = w & 1;
    const size_t row0 = (size_t)blockIdx.x * 128;
    const int cc = blockIdx.y * 64;

    wmma::fragment<wmma::accumulator,16,16,16,float> acc[2][2];
    #pragma unroll
    for (int mi = 0; mi < 2; mi++)
        #pragma unroll
        for (int ni = 0; ni < 2; ni++) wmma::fill_fragment(acc[mi][ni], 0.f);

    for (int kc = 0; kc < KTOT; kc += 64) {
        // A: 128x64 fp32 -> bf16 hi/lo
        #pragma unroll
        for (int it = 0; it < 8; it++) {
            int idx = t + it*256;           // 0..2047 float4
            int r = idx >> 4, c4 = idx & 15;
            float4 v = *(const float4*)(X + (row0 + r)*KTOT + kc + c4*4);
            __nv_bfloat162 h0 = __float22bfloat162_rn(make_float2(v.x, v.y));
            __nv_bfloat162 h1 = __float22bfloat162_rn(make_float2(v.z, v.w));
            float2 f0 = __bfloat1622float2(h0);
            float2 f1 = __bfloat1622float2(h1);
            __nv_bfloat162 l0 = __float22bfloat162_rn(make_float2(v.x - f0.x, v.y - f0.y));
            __nv_bfloat162 l1 = __float22bfloat162_rn(make_float2(v.z - f1.x, v.w - f1.y));
            uint2 hv, lv;
            hv.x = *reinterpret_cast<uint32_t*>(&h0);
            hv.y = *reinterpret_cast<uint32_t*>(&h1);
            lv.x = *reinterpret_cast<uint32_t*>(&l0);
            lv.y = *reinterpret_cast<uint32_t*>(&l1);
            *(uint2*)(Ahi + r*72 + c4*4) = hv;
            *(uint2*)(Alo + r*72 + c4*4) = lv;
        }
        // B: rows kc..kc+63, cols cc..cc+63 of split W
        #pragma unroll
        for (int it = 0; it < 2; it++) {
            int idx = t + it*256;           // 0..511, 8 bf16 each
            int r = idx >> 3, c8 = idx & 7;
            uint4 vh = *(const uint4*)(WHi + (size_t)(kc + r)*MTOT + cc + c8*8);
            uint4 vl = *(const uint4*)(WLo + (size_t)(kc + r)*MTOT + cc + c8*8);
            *(uint4*)(Bhi + r*72 + c8*8) = vh;
            *(uint4*)(Blo + r*72 + c8*8) = vl;
        }
        __syncthreads();

        #pragma unroll
        for (int ks = 0; ks < 4; ks++) {
            wmma::fragment<wmma::matrix_a,16,16,16,__nv_bfloat16,wmma::row_major> ah[2], al[2];
            wmma::fragment<wmma::matrix_b,16,16,16,__nv_bfloat16,wmma::row_major> bh[2], bl[2];
            #pragma unroll
            for (int mi = 0; mi < 2; mi++) {
                wmma::load_matrix_sync(ah[mi], Ahi + (wm*32 + mi*16)*72 + ks*16, 72);
                wmma::load_matrix_sync(al[mi], Alo + (wm*32 + mi*16)*72 + ks*16, 72);
            }
            #pragma unroll
            for (int ni = 0; ni < 2; ni++) {
                wmma::load_matrix_sync(bh[ni], Bhi + (ks*16)*72 + wn*32 + ni*16, 72);
                wmma::load_matrix_sync(bl[ni], Blo + (ks*16)*72 + wn*32 + ni*16, 72);
            }
            #pragma unroll
            for (int mi = 0; mi < 2; mi++)
                #pragma unroll
                for (int ni = 0; ni < 2; ni++) {
                    wmma::mma_sync(acc[mi][ni], ah[mi], bh[ni], acc[mi][ni]);
                    wmma::mma_sync(acc[mi][ni], ah[mi], bl[ni], acc[mi][ni]);
                    wmma::mma_sync(acc[mi][ni], al[mi], bh[ni], acc[mi][ni]);
                }
        }
        __syncthreads();
    }

    if constexpr (EPI == 2 || EPI == 3) {
        // full-row epilogue with LN; C shared [128][68]
        float* C = (float*)smw;
        #pragma unroll
        for (int mi = 0; mi < 2; mi++)
            #pragma unroll
            for (int ni = 0; ni < 2; ni++)
                wmma::store_matrix_sync(C + (wm*32 + mi*16)*68 + wn*32 + ni*16,
                                        acc[mi][ni], 68, wmma::mem_row_major);
        __syncthreads();

        #pragma unroll 1
        for (int i = 0; i < 16; i++) {
            int r = w*16 + i;
            size_t gr = row0 + r;
            float v0 = C[r*68 + lane]      + bias[lane];
            float v1 = C[r*68 + 32 + lane] + bias[32 + lane];
            if constexpr (EPI == 2) {
                v0 += res[gr*64 + lane];
                v1 += res[gr*64 + 32 + lane];
            } else {
                v0 = gelu_f(v0);
                v1 = gelu_f(v1);
                out[gr*64 + lane]      = v0;   // emb
                out[gr*64 + 32 + lane] = v1;
                int l = (int)(gr % LL);
                v0 += pos[l*64 + lane];
                v1 += pos[l*64 + 32 + lane];
            }
            float mean = wsum(v0 + v1) * (1.f/64.f);
            float d0 = v0 - mean, d1 = v1 - mean;
            float var = wsum(d0*d0 + d1*d1) * (1.f/64.f);
            float inv = rsqrtf(var + 1e-5f);
            float* dst = (EPI == 2) ? out : out2;
            dst[gr*64 + lane]      = d0*inv*gma[lane]    + bta[lane];
            dst[gr*64 + 32 + lane] = d1*inv*gma[lane+32] + bta[lane+32];
        }
    } else {
        // per-warp epilogue
        float* Cw = (float*)smw + w*(32*36);
        #pragma unroll
        for (int mi = 0; mi < 2; mi++)
            #pragma unroll
            for (int ni = 0; ni < 2; ni++)
                wmma::store_matrix_sync(Cw + mi*16*36 + ni*16, acc[mi][ni], 36,
                                        wmma::mem_row_major);
        __syncwarp();

        size_t gr = row0 + wm*32 + lane;
        #pragma unroll
        for (int c4 = 0; c4 < 8; c4++) {
            float v[4];
            #pragma unroll
            for (int u = 0; u < 4; u++) {
                v[u] = Cw[lane*36 + c4*4 + u] + __ldg(bias + cc + wn*32 + c4*4 + u);
                if (EPI == 1) v[u] = gelu_f(v[u]);
            }
            *(float4*)(out + gr*MTOT + cc + wn*32 + c4*4) = make_float4(v[0],v[1],v[2],v[3]);
        }
    }
}

// ---------------- attention (unchanged) ----------------
__global__ void __launch_bounds__(256) attn_kernel(const float* __restrict__ qkv,
        const int* __restrict__ mask, float* __restrict__ O)
{
    extern __shared__ float sm[];
    float* Sc  = sm;                      // 8 * 204*8
    float* Qw  = Sc + 8*204*8;            // 8 * 256
    float* Inv = Qw + 8*256;              // 64
    float* Ks  = Inv + 64;                // 201*33
    float* Vs  = Ks + 201*33;             // 201*33
    float* Ms  = Vs + 201*33;             // 201

    int bh = blockIdx.x;
    int b = bh >> 1, h = bh & 1;
    const float* base = qkv + (size_t)b*LL*192;
    int t = threadIdx.x;

    for (int i = t; i < LL*32; i += 256) {
        int j = i >> 5, d = i & 31;
        Ks[j*33 + d] = base[j*192 + 64  + h*32 + d];
        Vs[j*33 + d] = base[j*192 + 128 + h*32 + d];
    }
    for (int i = t; i < LL; i += 256) Ms[i] = (float)mask[b*LL + i];
    __syncthreads();

    int w = t >> 5, lane = t & 31;
    float* sc = Sc + w*204*8;
    float* qw = Qw + w*256;
    const float scale = 0.17677669529663687f;

    for (int g = w; g < 26; g += 8) {
        int base_q = g*8;
        #pragma unroll
        for (int q = 0; q < 8; q++) {
            int lq = min(base_q + q, LL-1);
            qw[lane*8 + q] = base[(size_t)lq*192 + h*32 + lane];
        }
        __syncwarp();

        int jmax = min(LL, base_q + 8);

        auto scorepass = [&](int jhi) {
            for (int j0 = 0; j0 < jhi; j0 += 32) {
                int j = j0 + lane;
                if (j < jhi) {
                    float dot[8];
                    #pragma unroll
                    for (int q = 0; q < 8; q++) dot[q] = 0.f;
                    #pragma unroll
                    for (int d = 0; d < 32; d++) {
                        float kv = Ks[j*33 + d];
                        float4 qa = *(const float4*)(qw + d*8);
                        float4 qb = *(const float4*)(qw + d*8 + 4);
                        dot[0] = fmaf(kv, qa.x, dot[0]);
                        dot[1] = fmaf(kv, qa.y, dot[1]);
                        dot[2] = fmaf(kv, qa.z, dot[2]);
                        dot[3] = fmaf(kv, qa.w, dot[3]);
                        dot[4] = fmaf(kv, qb.x, dot[4]);
                        dot[5] = fmaf(kv, qb.y, dot[5]);
                        dot[6] = fmaf(kv, qb.z, dot[6]);
                        dot[7] = fmaf(kv, qb.w, dot[7]);
                    }
                    float m = Ms[j];
                    float s8[8];
                    #pragma unroll
                    for (int q = 0; q < 8; q++) {
                        int lq = min(base_q + q, LL-1);
                        bool allowed = (j <= lq) && (m > 0.f);
                        s8[q] = dot[q]*scale + (allowed ? 0.f : -1e9f);
                    }
                    *(float4*)(sc + j*8)     = make_float4(s8[0],s8[1],s8[2],s8[3]);
                    *(float4*)(sc + j*8 + 4) = make_float4(s8[4],s8[5],s8[6],s8[7]);
                }
            }
        };

        scorepass(jmax);
        __syncwarp();

        int qi = lane & 7, jo = lane >> 3;
        auto reduce_mx = [&](int jlen) {
            float mx = -INFINITY;
            for (int j = jo; j < jlen; j += 4) mx = fmaxf(mx, sc[j*8 + qi]);
            mx = fmaxf(mx, __shfl_xor_sync(0xffffffffu, mx, 8));
            mx = fmaxf(mx, __shfl_xor_sync(0xffffffffu, mx, 16));
            return mx;
        };
        float mx = reduce_mx(jmax);
        int jlen = jmax;
        if (__any_sync(0xffffffffu, mx < -1e8f)) {
            jlen = LL;
            scorepass(LL);
            __syncwarp();
            mx = reduce_mx(LL);
        }

        float s = 0.f;
        for (int j = jo; j < jlen; j += 4) {
            float e = __expf(sc[j*8 + qi] - mx);
            sc[j*8 + qi] = e;
            s += e;
        }
        s += __shfl_xor_sync(0xffffffffu, s, 8);
        s += __shfl_xor_sync(0xffffffffu, s, 16);
        if (lane < 8) Inv[w*8 + lane] = 1.f / s;
        __syncwarp();

        float acc[8];
        #pragma unroll
        for (int q = 0; q < 8; q++) acc[q] = 0.f;
        for (int j = 0; j < jlen; j++) {
            float v = Vs[j*33 + lane];
            float4 pa = *(const float4*)(sc + j*8);
            float4 pb = *(const float4*)(sc + j*8 + 4);
            acc[0] = fmaf(pa.x, v, acc[0]);
            acc[1] = fmaf(pa.y, v, acc[1]);
            acc[2] = fmaf(pa.z, v, acc[2]);
            acc[3] = fmaf(pa.w, v, acc[3]);
            acc[4] = fmaf(pb.x, v, acc[4]);
            acc[5] = fmaf(pb.y, v, acc[5]);
            acc[6] = fmaf(pb.z, v, acc[6]);
            acc[7] = fmaf(pb.w, v, acc[7]);
        }
        #pragma unroll
        for (int q = 0; q < 8; q++) {
            int lq = min(base_q + q, LL-1);
            O[((size_t)b*LL + lq)*64 + h*32 + lane] = acc[q] * Inv[w*8 + q];
        }
        __syncwarp();
    }
}

// ---------------- masked sum of interaction_list over L ----------------
__global__ void xsum_kernel(const float* __restrict__ X, const int* __restrict__ mask,
                            float* __restrict__ Xsum)
{
    int b = blockIdx.x;
    int d4 = threadIdx.x;
    const float* xb = X + (size_t)b*LL*DD;
    float4 acc = make_float4(0.f,0.f,0.f,0.f);
    for (int l = 0; l < LL; l++) {
        if (mask[b*LL + l]) {
            float4 v = *(const float4*)(xb + (size_t)l*DD + d4*4);
            acc.x += v.x; acc.y += v.y; acc.z += v.z; acc.w += v.w;
        }
    }
    *(float4*)(Xsum + (size_t)b*DD + d4*4) = acc;
}

// ---------------- collapsed GNN ----------------
__global__ void gnn_kernel(const float* __restrict__ Xsum, const int* __restrict__ mask,
                           const float* __restrict__ wg1, const float* __restrict__ bg1,
                           const float* __restrict__ wg2, float* __restrict__ uon)
{
    __shared__ float xs[DD];
    __shared__ float h1[FF];
    __shared__ int   Scnt;
    int b = blockIdx.x, t = threadIdx.x;
    for (int i = t; i < DD; i += 256) xs[i] = Xsum[(size_t)b*DD + i];
    int cnt = 0;
    for (int l = t; l < LL; l += 256) cnt += mask[b*LL + l];
    if (t == 0) Scnt = 0;
    __syncthreads();
    if (cnt) atomicAdd(&Scnt, cnt);
    __syncthreads();
    float S = (float)Scnt;
    float scale = S > 0.f ? 1.f/S : 0.f;
    float mg = 0.f;
    for (int k = 0; k < DD; k++) mg += xs[k] * wg1[(size_t)k*FF + t];
    h1[t] = fmaxf(mg*scale + bg1[t], 0.f);
    __syncthreads();
    if (t < 64) {
        float u = 0.f;
        for (int f = 0; f < FF; f++) u += h1[f] * wg2[(size_t)f*64 + t];
        uon[b*64 + t] = (S > 0.f) ? u : 0.f;
    }
}

// ---------------- similarity ----------------
__global__ void sim_kernel(const float* __restrict__ emb, const float* __restrict__ uon,
                           const float* __restrict__ bg2, const int* __restrict__ mask,
                           float* __restrict__ partial)
{
    __shared__ float ps[8];
    int w = threadIdx.x >> 5, lane = threadIdx.x & 31;
    int row = blockIdx.x * 8 + w;
    float c = 0.f;
    if (row < NTOT) {
        int b = row / LL;
        float m = (float)mask[row];
        float e0 = emb[(size_t)row*64 + lane];
        float e1 = emb[(size_t)row*64 + 32 + lane];
        float g0 = m*uon[b*64 + lane]      + bg2[lane];
        float g1 = m*uon[b*64 + 32 + lane] + bg2[lane+32];
        float num = wsum(e0*g0 + e1*g1);
        float na  = wsum(e0*e0 + e1*e1);
        float nb  = wsum(g0*g0 + g1*g1);
        na = fmaxf(sqrtf(na), 1e-8f);
        nb = fmaxf(sqrtf(nb), 1e-8f);
        c = num / (na*nb);
    }
    if (lane == 0) ps[w] = c;
    __syncthreads();
    if (threadIdx.x == 0) {
        float s = 0.f;
        #pragma unroll
        for (int i = 0; i < 8; i++) s += ps[i];
        partial[blockIdx.x] = s;
    }
}

__global__ void sim_reduce(const float* __restrict__ partial, float* __restrict__ out)
{
    __shared__ float smem[256];
    float s = 0.f;
    for (int i = threadIdx.x; i < 6432; i += 256) s += partial[i];
    smem[threadIdx.x] = s;
    __syncthreads();
    for (int o = 128; o; o >>= 1) {
        if (threadIdx.x < o) smem[threadIdx.x] += smem[threadIdx.x + o];
        __syncthreads();
    }
    if (threadIdx.x == 0) out[0] = smem[0] / (float)(LL*BB);
}

// ---------------- output assembly ----------------
__global__ void out_kernel(const float* __restrict__ emb, const float* __restrict__ x,
                           const float* __restrict__ negE, float* __restrict__ out)
{
    int row = blockIdx.x;
    int t = threadIdx.x;   // 64
    int b = row / LL, l = row % LL;
    float e  = emb[(size_t)row*64 + t];
    float xv = x[(size_t)row*64 + t];
    out[OFF4 + (size_t)row*128 + t]      = e;
    out[OFF4 + (size_t)row*128 + 64 + t] = xv;
    if (l < LL-1) {
        size_t r200 = (size_t)b*(LL-1) + l;
        out[OFF1 + r200*64 + t] = xv;
        out[OFF2 + r200*64 + t] = emb[((size_t)b*LL + l + 1)*64 + t];
        out[OFF3 + r200*64 + t] = negE[(size_t)row*64 + t];
    }
}

// ---------------- host ----------------
template <typename T>
static void* symaddr_v(T& sym){ void* p = nullptr; cudaGetSymbolAddress(&p, sym); return p; }

extern "C" void kernel_launch(void* const* d_in, const int* in_sizes, int n_in,
                              void* d_out, int out_size)
{
    const float* inter = (const float*)d_in[0];
    const float* neg   = (const float*)d_in[1];
    const float* fc_w  = (const float*)d_in[2];
    const float* fc_b  = (const float*)d_in[3];
    const float* mlp_w = (const float*)d_in[4];
    const float* mlp_b = (const float*)d_in[5];
    const float* pos   = (const float*)d_in[6];
    const float* ln0g  = (const float*)d_in[7];
    const float* ln0b  = (const float*)d_in[8];
    const float* wqkv  = (const float*)d_in[9];
    const float* bqkv  = (const float*)d_in[10];
    const float* wo    = (const float*)d_in[11];
    const float* bo    = (const float*)d_in[12];
    const float* ln1g  = (const float*)d_in[13];
    const float* ln1b  = (const float*)d_in[14];
    const float* w1    = (const float*)d_in[15];
    const float* b1    = (const float*)d_in[16];
    const float* w2    = (const float*)d_in[17];
    const float* b2    = (const float*)d_in[18];
    const float* ln2g  = (const float*)d_in[19];
    const float* ln2b  = (const float*)d_in[20];
    const float* wg1   = (const float*)d_in[21];
    const float* bg1   = (const float*)d_in[22];
    const float* wg2   = (const float*)d_in[23];
    const float* bg2   = (const float*)d_in[24];
    const int*   mask  = (const int*)d_in[25];
    float* out = (float*)d_out;

    float* T1   = (float*)symaddr_v(g_T1);
    float* Tneg = (float*)symaddr_v(g_Tneg);
    float* emb  = (float*)symaddr_v(g_emb);
    float* negE = (float*)symaddr_v(g_negE);
    float* x    = (float*)symaddr_v(g_x);
    float* qkvb = (float*)symaddr_v(g_qkv);
    float* attO = (float*)symaddr_v(g_attn);
    float* ff1  = (float*)symaddr_v(g_ff1);
    float* Xsum = (float*)symaddr_v(g_xsum);
    float* uon  = (float*)symaddr_v(g_uon);
    float* part = (float*)symaddr_v(g_part);
    __nv_bfloat16* WHi = (__nv_bfloat16*)symaddr_v(g_WHi);
    __nv_bfloat16* WLo = (__nv_bfloat16*)symaddr_v(g_WLo);

    const int SMEM_W = (2*128*72 + 2*64*72) * 2;  // 55296
    const int SMEM_A = (8*204*8 + 8*256 + 64 + 201*33*2 + 201) * 4; // 114540

    cudaFuncSetAttribute((const void*)gemm_w<1536,64,0>,
                         cudaFuncAttributeMaxDynamicSharedMemorySize, SMEM_W);
    cudaFuncSetAttribute((const void*)gemm_w<64,64,1>,
                         cudaFuncAttributeMaxDynamicSharedMemorySize, SMEM_W);
    cudaFuncSetAttribute((const void*)gemm_w<64,64,3>,
                         cudaFuncAttributeMaxDynamicSharedMemorySize, SMEM_W);
    cudaFuncSetAttribute((const void*)gemm_w<64,192,0>,
                         cudaFuncAttributeMaxDynamicSharedMemorySize, SMEM_W);
    cudaFuncSetAttribute((const void*)gemm_w<64,64,2>,
                         cudaFuncAttributeMaxDynamicSharedMemorySize, SMEM_W);
    cudaFuncSetAttribute((const void*)gemm_w<64,256,1>,
                         cudaFuncAttributeMaxDynamicSharedMemorySize, SMEM_W);
    cudaFuncSetAttribute((const void*)gemm_w<256,64,2>,
                         cudaFuncAttributeMaxDynamicSharedMemorySize, SMEM_W);
    cudaFuncSetAttribute((const void*)attn_kernel,
                         cudaFuncAttributeMaxDynamicSharedMemorySize, SMEM_A);

    const int GT = NTOT/128;   // 402
    const int GL = NTOT/8;     // 6432

    // weight conversion (fp32 -> bf16 hi/lo)
    wconv_kernel<<<384, 256>>>(fc_w,  WHi + OFC,  WLo + OFC,  98304);
    wconv_kernel<<<16,  256>>>(mlp_w, WHi + OMLP, WLo + OMLP, 4096);
    wconv_kernel<<<96,  256>>>(wqkv,  WHi + OQKV, WLo + OQKV, 24576);
    wconv_kernel<<<32,  256>>>(wo,    WHi + OWO,  WLo + OWO,  8192);
    wconv_kernel<<<128, 256>>>(w1,    WHi + OW1,  WLo + OW1,  32768);
    wconv_kernel<<<128, 256>>>(w2,    WHi + OW2,  WLo + OW2,  32768);

    // embedding towers
    gemm_w<1536,64,0><<<dim3(GT,1), 256, SMEM_W>>>(inter, WHi+OFC, WLo+OFC, fc_b,
            nullptr, nullptr, nullptr, nullptr, T1, nullptr);
    gemm_w<1536,64,0><<<dim3(GT,1), 256, SMEM_W>>>(neg, WHi+OFC, WLo+OFC, fc_b,
            nullptr, nullptr, nullptr, nullptr, Tneg, nullptr);
    // emb = gelu(T1@mlp), x = LN(emb + pos)
    gemm_w<64,64,3><<<dim3(GT,1), 256, SMEM_W>>>(T1, WHi+OMLP, WLo+OMLP, mlp_b,
            nullptr, ln0g, ln0b, pos, emb, x);
    gemm_w<64,64,1><<<dim3(GT,1), 256, SMEM_W>>>(Tneg, WHi+OMLP, WLo+OMLP, mlp_b,
            nullptr, nullptr, nullptr, nullptr, negE, nullptr);

    // collapsed GNN + similarity
    xsum_kernel<<<BB, 384>>>(inter, mask, Xsum);
    gnn_kernel<<<BB, 256>>>(Xsum, mask, wg1, bg1, wg2, uon);
    sim_kernel<<<GL, 256>>>(emb, uon, bg2, mask, part);
    sim_reduce<<<1, 256>>>(part, out + SIMO);

    // encoder (LN fused into wo / w2 epilogues)
    for (int i = 0; i < 2; i++) {
        gemm_w<64,192,0><<<dim3(GT,3), 256, SMEM_W>>>(x, WHi+OQKV+(size_t)i*12288,
                WLo+OQKV+(size_t)i*12288, bqkv + i*192,
                nullptr, nullptr, nullptr, nullptr, qkvb, nullptr);
        attn_kernel<<<BB*NHD, 256, SMEM_A>>>(qkvb, mask, attO);
        gemm_w<64,64,2><<<dim3(GT,1), 256, SMEM_W>>>(attO, WHi+OWO+(size_t)i*4096,
                WLo+OWO+(size_t)i*4096, bo + i*64,
                x, ln1g + i*64, ln1b + i*64, nullptr, x, nullptr);
        gemm_w<64,256,1><<<dim3(GT,4), 256, SMEM_W>>>(x, WHi+OW1+(size_t)i*16384,
                WLo+OW1+(size_t)i*16384, b1 + i*256,
                nullptr, nullptr, nullptr, nullptr, ff1, nullptr);
        gemm_w<256,64,2><<<dim3(GT,1), 256, SMEM_W>>>(ff1, WHi+OW2+(size_t)i*16384,
                WLo+OW2+(size_t)i*16384, b2 + i*64,
                x, ln2g + i*64, ln2b + i*64, nullptr, x, nullptr);
    }

    out_kernel<<<NTOT, 64>>>(emb, x, negE, out);
}

// round 11
// speedup vs baseline: 3.8751x; 1.0641x over previous
#include <cuda_runtime.h>
#include <cuda_bf16.h>
#include <mma.h>
#include <math.h>
#include <stdint.h>

using namespace nvcuda;

// ---------------- problem constants ----------------
#define BB   256
#define LL   201
#define DD   1536
#define HH   64
#define NHD  2
#define DH   32
#define FF   256
#define NTOT (BB*LL)          // 51456 = 128 * 402

// output offsets (float elements)
#define OFF1 0
#define OFF2 3276800
#define OFF3 6553600
#define OFF4 9830400
#define SIMO 16416768

// weight scratch offsets (elements)
#define OFC   0
#define OMLP  98304
#define OQKV  102400
#define OWO   126976
#define OW1   135168
#define OW2   167936
#define WTOT  200704

// ---------------- scratch ----------------
__device__ float g_T1  [NTOT*HH];
__device__ float g_Tneg[NTOT*HH];
__device__ float g_emb [NTOT*HH];
__device__ float g_negE[NTOT*HH];
__device__ float g_x   [NTOT*HH];
__device__ float g_qkv [NTOT*192];
__device__ float g_attn[NTOT*HH];
__device__ float g_ff1 [NTOT*FF];
__device__ float g_xsum3[3*BB*DD];
__device__ float g_uon [BB*HH];
__device__ float g_part[6432];
__device__ __nv_bfloat16 g_WHi[WTOT];
__device__ __nv_bfloat16 g_WLo[WTOT];

// ---------------- helpers ----------------
__device__ __forceinline__ float wsum(float v){
    #pragma unroll
    for (int o = 16; o; o >>= 1) v += __shfl_xor_sync(0xffffffffu, v, o);
    return v;
}
__device__ __forceinline__ float gelu_f(float x){
    float x3 = x*x*x;
    return 0.5f*x*(1.f + tanhf(0.7978845608028654f*(x + 0.044715f*x3)));
}

// ---------------- merged W prep: all weights -> hi/lo bf16 ----------------
__global__ void wconv_all(const float* __restrict__ fc_w, const float* __restrict__ mlp_w,
                          const float* __restrict__ wqkv, const float* __restrict__ wo,
                          const float* __restrict__ w1,   const float* __restrict__ w2,
                          __nv_bfloat16* __restrict__ Hi, __nv_bfloat16* __restrict__ Lo)
{
    int idx = blockIdx.x*256 + threadIdx.x;
    if (idx >= WTOT) return;
    const float* src; int off;
    if      (idx < OMLP) { src = fc_w;  off = idx; }
    else if (idx < OQKV) { src = mlp_w; off = idx - OMLP; }
    else if (idx < OWO)  { src = wqkv;  off = idx - OQKV; }
    else if (idx < OW1)  { src = wo;    off = idx - OWO; }
    else if (idx < OW2)  { src = w1;    off = idx - OW1; }
    else                 { src = w2;    off = idx - OW2; }
    float w = src[off];
    __nv_bfloat16 h = __float2bfloat16(w);
    Hi[idx] = h;
    Lo[idx] = __float2bfloat16(w - __bfloat162float(h));
}

// ---------------- unified wmma GEMM (bf16x3, fp32 accum) ----------------
// out[N, MTOT] = X[N, KTOT] @ W[KTOT, MTOT] + bias, with fused epilogues.
// EPI: 0 = bias only (dual-input capable: X2/out3 for second grid half)
//      1 = gelu(bias+..)
//      2 = out = LN(res + gemm + bias; gma, bta)         (MTOT == 64)
//      3 = out = gelu(gemm+bias); out2 = LN(out + pos)   (MTOT == 64)
//      4 = dual: first half = EPI3 (X->out,out2); second half = gelu (X2->out3)
// CTA: 128 rows x 64 cols (grid.y = MTOT/64), 8 warps in 4x2.
template<int KTOT, int MTOT, int EPI>
__global__ void __launch_bounds__(256, 2) gemm_w(const float* __restrict__ X,
        const float* __restrict__ X2,
        const __nv_bfloat16* __restrict__ WHi, const __nv_bfloat16* __restrict__ WLo,
        const float* __restrict__ bias, const float* __restrict__ res,
        const float* __restrict__ gma, const float* __restrict__ bta,
        const float* __restrict__ pos,
        float* __restrict__ out, float* __restrict__ out2, float* __restrict__ out3)
{
    extern __shared__ char smw[];
    __nv_bfloat16* Ahi = (__nv_bfloat16*)smw;       // 128*72
    __nv_bfloat16* Alo = Ahi + 128*72;
    __nv_bfloat16* Bhi = Alo + 128*72;              // 64*72
    __nv_bfloat16* Blo = Bhi + 64*72;

    const int t = threadIdx.x;
    const int w = t >> 5, lane = t & 31;
    const int wm = w >> 1, wn = w & 1;
    const bool second = (X2 != nullptr) && ((int)blockIdx.x >= ((int)gridDim.x >> 1));
    const int bx = second ? (int)blockIdx.x - ((int)gridDim.x >> 1) : (int)blockIdx.x;
    const size_t row0 = (size_t)bx * 128;
    const int cc = blockIdx.y * 64;
    const float* Xe = second ? X2 : X;

    wmma::fragment<wmma::accumulator,16,16,16,float> acc[2][2];
    #pragma unroll
    for (int mi = 0; mi < 2; mi++)
        #pragma unroll
        for (int ni = 0; ni < 2; ni++) wmma::fill_fragment(acc[mi][ni], 0.f);

    for (int kc = 0; kc < KTOT; kc += 64) {
        // A: 128x64 fp32 -> bf16 hi/lo
        #pragma unroll
        for (int it = 0; it < 8; it++) {
            int idx = t + it*256;           // 0..2047 float4
            int r = idx >> 4, c4 = idx & 15;
            float4 v = *(const float4*)(Xe + (row0 + r)*KTOT + kc + c4*4);
            __nv_bfloat162 h0 = __float22bfloat162_rn(make_float2(v.x, v.y));
            __nv_bfloat162 h1 = __float22bfloat162_rn(make_float2(v.z, v.w));
            float2 f0 = __bfloat1622float2(h0);
            float2 f1 = __bfloat1622float2(h1);
            __nv_bfloat162 l0 = __float22bfloat162_rn(make_float2(v.x - f0.x, v.y - f0.y));
            __nv_bfloat162 l1 = __float22bfloat162_rn(make_float2(v.z - f1.x, v.w - f1.y));
            uint2 hv, lv;
            hv.x = *reinterpret_cast<uint32_t*>(&h0);
            hv.y = *reinterpret_cast<uint32_t*>(&h1);
            lv.x = *reinterpret_cast<uint32_t*>(&l0);
            lv.y = *reinterpret_cast<uint32_t*>(&l1);
            *(uint2*)(Ahi + r*72 + c4*4) = hv;
            *(uint2*)(Alo + r*72 + c4*4) = lv;
        }
        // B: rows kc..kc+63, cols cc..cc+63 of split W
        #pragma unroll
        for (int it = 0; it < 2; it++) {
            int idx = t + it*256;           // 0..511, 8 bf16 each
            int r = idx >> 3, c8 = idx & 7;
            uint4 vh = *(const uint4*)(WHi + (size_t)(kc + r)*MTOT + cc + c8*8);
            uint4 vl = *(const uint4*)(WLo + (size_t)(kc + r)*MTOT + cc + c8*8);
            *(uint4*)(Bhi + r*72 + c8*8) = vh;
            *(uint4*)(Blo + r*72 + c8*8) = vl;
        }
        __syncthreads();

        #pragma unroll
        for (int ks = 0; ks < 4; ks++) {
            wmma::fragment<wmma::matrix_a,16,16,16,__nv_bfloat16,wmma::row_major> ah[2], al[2];
            wmma::fragment<wmma::matrix_b,16,16,16,__nv_bfloat16,wmma::row_major> bh[2], bl[2];
            #pragma unroll
            for (int mi = 0; mi < 2; mi++) {
                wmma::load_matrix_sync(ah[mi], Ahi + (wm*32 + mi*16)*72 + ks*16, 72);
                wmma::load_matrix_sync(al[mi], Alo + (wm*32 + mi*16)*72 + ks*16, 72);
            }
            #pragma unroll
            for (int ni = 0; ni < 2; ni++) {
                wmma::load_matrix_sync(bh[ni], Bhi + (ks*16)*72 + wn*32 + ni*16, 72);
                wmma::load_matrix_sync(bl[ni], Blo + (ks*16)*72 + wn*32 + ni*16, 72);
            }
            #pragma unroll
            for (int mi = 0; mi < 2; mi++)
                #pragma unroll
                for (int ni = 0; ni < 2; ni++) {
                    wmma::mma_sync(acc[mi][ni], ah[mi], bh[ni], acc[mi][ni]);
                    wmma::mma_sync(acc[mi][ni], ah[mi], bl[ni], acc[mi][ni]);
                    wmma::mma_sync(acc[mi][ni], al[mi], bh[ni], acc[mi][ni]);
                }
        }
        __syncthreads();
    }

    if constexpr (EPI == 2 || EPI == 3 || EPI == 4) {
        // full-row epilogue; C shared [128][68]
        float* C = (float*)smw;
        #pragma unroll
        for (int mi = 0; mi < 2; mi++)
            #pragma unroll
            for (int ni = 0; ni < 2; ni++)
                wmma::store_matrix_sync(C + (wm*32 + mi*16)*68 + wn*32 + ni*16,
                                        acc[mi][ni], 68, wmma::mem_row_major);
        __syncthreads();

        #pragma unroll 1
        for (int i = 0; i < 16; i++) {
            int r = w*16 + i;
            size_t gr = row0 + r;
            float v0 = C[r*68 + lane]      + bias[lane];
            float v1 = C[r*68 + 32 + lane] + bias[32 + lane];
            if constexpr (EPI == 2) {
                v0 += res[gr*64 + lane];
                v1 += res[gr*64 + 32 + lane];
            } else {
                v0 = gelu_f(v0);
                v1 = gelu_f(v1);
                if (EPI == 4 && second) {
                    out3[gr*64 + lane]      = v0;   // negE
                    out3[gr*64 + 32 + lane] = v1;
                    continue;
                }
                out[gr*64 + lane]      = v0;   // emb
                out[gr*64 + 32 + lane] = v1;
                int l = (int)(gr % LL);
                v0 += pos[l*64 + lane];
                v1 += pos[l*64 + 32 + lane];
            }
            float mean = wsum(v0 + v1) * (1.f/64.f);
            float d0 = v0 - mean, d1 = v1 - mean;
            float var = wsum(d0*d0 + d1*d1) * (1.f/64.f);
            float inv = rsqrtf(var + 1e-5f);
            float* dst = (EPI == 2) ? out : out2;
            dst[gr*64 + lane]      = d0*inv*gma[lane]    + bta[lane];
            dst[gr*64 + 32 + lane] = d1*inv*gma[lane+32] + bta[lane+32];
        }
    } else {
        // per-warp epilogue
        float* Cw = (float*)smw + w*(32*36);
        #pragma unroll
        for (int mi = 0; mi < 2; mi++)
            #pragma unroll
            for (int ni = 0; ni < 2; ni++)
                wmma::store_matrix_sync(Cw + mi*16*36 + ni*16, acc[mi][ni], 36,
                                        wmma::mem_row_major);
        __syncwarp();

        float* dst = second ? out3 : out;
        size_t gr = row0 + wm*32 + lane;
        #pragma unroll
        for (int c4 = 0; c4 < 8; c4++) {
            float v[4];
            #pragma unroll
            for (int u = 0; u < 4; u++) {
                v[u] = Cw[lane*36 + c4*4 + u] + __ldg(bias + cc + wn*32 + c4*4 + u);
                if (EPI == 1) v[u] = gelu_f(v[u]);
            }
            *(float4*)(dst + gr*MTOT + cc + wn*32 + c4*4) = make_float4(v[0],v[1],v[2],v[3]);
        }
    }
}

// ---------------- attention (unchanged) ----------------
__global__ void __launch_bounds__(256) attn_kernel(const float* __restrict__ qkv,
        const int* __restrict__ mask, float* __restrict__ O)
{
    extern __shared__ float sm[];
    float* Sc  = sm;                      // 8 * 204*8
    float* Qw  = Sc + 8*204*8;            // 8 * 256
    float* Inv = Qw + 8*256;              // 64
    float* Ks  = Inv + 64;                // 201*33
    float* Vs  = Ks + 201*33;             // 201*33
    float* Ms  = Vs + 201*33;             // 201

    int bh = blockIdx.x;
    int b = bh >> 1, h = bh & 1;
    const float* base = qkv + (size_t)b*LL*192;
    int t = threadIdx.x;

    for (int i = t; i < LL*32; i += 256) {
        int j = i >> 5, d = i & 31;
        Ks[j*33 + d] = base[j*192 + 64  + h*32 + d];
        Vs[j*33 + d] = base[j*192 + 128 + h*32 + d];
    }
    for (int i = t; i < LL; i += 256) Ms[i] = (float)mask[b*LL + i];
    __syncthreads();

    int w = t >> 5, lane = t & 31;
    float* sc = Sc + w*204*8;
    float* qw = Qw + w*256;
    const float scale = 0.17677669529663687f;

    for (int g = w; g < 26; g += 8) {
        int base_q = g*8;
        #pragma unroll
        for (int q = 0; q < 8; q++) {
            int lq = min(base_q + q, LL-1);
            qw[lane*8 + q] = base[(size_t)lq*192 + h*32 + lane];
        }
        __syncwarp();

        int jmax = min(LL, base_q + 8);

        auto scorepass = [&](int jhi) {
            for (int j0 = 0; j0 < jhi; j0 += 32) {
                int j = j0 + lane;
                if (j < jhi) {
                    float dot[8];
                    #pragma unroll
                    for (int q = 0; q < 8; q++) dot[q] = 0.f;
                    #pragma unroll
                    for (int d = 0; d < 32; d++) {
                        float kv = Ks[j*33 + d];
                        float4 qa = *(const float4*)(qw + d*8);
                        float4 qb = *(const float4*)(qw + d*8 + 4);
                        dot[0] = fmaf(kv, qa.x, dot[0]);
                        dot[1] = fmaf(kv, qa.y, dot[1]);
                        dot[2] = fmaf(kv, qa.z, dot[2]);
                        dot[3] = fmaf(kv, qa.w, dot[3]);
                        dot[4] = fmaf(kv, qb.x, dot[4]);
                        dot[5] = fmaf(kv, qb.y, dot[5]);
                        dot[6] = fmaf(kv, qb.z, dot[6]);
                        dot[7] = fmaf(kv, qb.w, dot[7]);
                    }
                    float m = Ms[j];
                    float s8[8];
                    #pragma unroll
                    for (int q = 0; q < 8; q++) {
                        int lq = min(base_q + q, LL-1);
                        bool allowed = (j <= lq) && (m > 0.f);
                        s8[q] = dot[q]*scale + (allowed ? 0.f : -1e9f);
                    }
                    *(float4*)(sc + j*8)     = make_float4(s8[0],s8[1],s8[2],s8[3]);
                    *(float4*)(sc + j*8 + 4) = make_float4(s8[4],s8[5],s8[6],s8[7]);
                }
            }
        };

        scorepass(jmax);
        __syncwarp();

        int qi = lane & 7, jo = lane >> 3;
        auto reduce_mx = [&](int jlen) {
            float mx = -INFINITY;
            for (int j = jo; j < jlen; j += 4) mx = fmaxf(mx, sc[j*8 + qi]);
            mx = fmaxf(mx, __shfl_xor_sync(0xffffffffu, mx, 8));
            mx = fmaxf(mx, __shfl_xor_sync(0xffffffffu, mx, 16));
            return mx;
        };
        float mx = reduce_mx(jmax);
        int jlen = jmax;
        if (__any_sync(0xffffffffu, mx < -1e8f)) {
            jlen = LL;
            scorepass(LL);
            __syncwarp();
            mx = reduce_mx(LL);
        }

        float s = 0.f;
        for (int j = jo; j < jlen; j += 4) {
            float e = __expf(sc[j*8 + qi] - mx);
            sc[j*8 + qi] = e;
            s += e;
        }
        s += __shfl_xor_sync(0xffffffffu, s, 8);
        s += __shfl_xor_sync(0xffffffffu, s, 16);
        if (lane < 8) Inv[w*8 + lane] = 1.f / s;
        __syncwarp();

        float acc[8];
        #pragma unroll
        for (int q = 0; q < 8; q++) acc[q] = 0.f;
        for (int j = 0; j < jlen; j++) {
            float v = Vs[j*33 + lane];
            float4 pa = *(const float4*)(sc + j*8);
            float4 pb = *(const float4*)(sc + j*8 + 4);
            acc[0] = fmaf(pa.x, v, acc[0]);
            acc[1] = fmaf(pa.y, v, acc[1]);
            acc[2] = fmaf(pa.z, v, acc[2]);
            acc[3] = fmaf(pa.w, v, acc[3]);
            acc[4] = fmaf(pb.x, v, acc[4]);
            acc[5] = fmaf(pb.y, v, acc[5]);
            acc[6] = fmaf(pb.z, v, acc[6]);
            acc[7] = fmaf(pb.w, v, acc[7]);
        }
        #pragma unroll
        for (int q = 0; q < 8; q++) {
            int lq = min(base_q + q, LL-1);
            O[((size_t)b*LL + lq)*64 + h*32 + lane] = acc[q] * Inv[w*8 + q];
        }
        __syncwarp();
    }
}

// ---------------- masked sum of interaction_list over L (3-way split) ----------------
__global__ void xsum_kernel(const float* __restrict__ X, const int* __restrict__ mask,
                            float* __restrict__ Xsum3)
{
    int b = blockIdx.x;
    int seg = blockIdx.y;
    int l0 = seg*67, l1 = min(LL, l0 + 67);
    int d4 = threadIdx.x;           // 384 threads * 4 = 1536
    const float* xb = X + (size_t)b*LL*DD;
    float4 acc = make_float4(0.f,0.f,0.f,0.f);
    for (int l = l0; l < l1; l++) {
        if (mask[b*LL + l]) {
            float4 v = *(const float4*)(xb + (size_t)l*DD + d4*4);
            acc.x += v.x; acc.y += v.y; acc.z += v.z; acc.w += v.w;
        }
    }
    *(float4*)(Xsum3 + ((size_t)seg*BB + b)*DD + d4*4) = acc;
}

// ---------------- collapsed GNN ----------------
__global__ void gnn_kernel(const float* __restrict__ Xsum3, const int* __restrict__ mask,
                           const float* __restrict__ wg1, const float* __restrict__ bg1,
                           const float* __restrict__ wg2, float* __restrict__ uon)
{
    __shared__ float xs[DD];
    __shared__ float h1[FF];
    __shared__ int   Scnt;
    int b = blockIdx.x, t = threadIdx.x;
    for (int i = t; i < DD; i += 256)
        xs[i] = Xsum3[(size_t)b*DD + i]
              + Xsum3[((size_t)BB + b)*DD + i]
              + Xsum3[((size_t)2*BB + b)*DD + i];
    int cnt = 0;
    for (int l = t; l < LL; l += 256) cnt += mask[b*LL + l];
    if (t == 0) Scnt = 0;
    __syncthreads();
    if (cnt) atomicAdd(&Scnt, cnt);
    __syncthreads();
    float S = (float)Scnt;
    float scale = S > 0.f ? 1.f/S : 0.f;
    float mg = 0.f;
    for (int k = 0; k < DD; k++) mg += xs[k] * wg1[(size_t)k*FF + t];
    h1[t] = fmaxf(mg*scale + bg1[t], 0.f);
    __syncthreads();
    if (t < 64) {
        float u = 0.f;
        for (int f = 0; f < FF; f++) u += h1[f] * wg2[(size_t)f*64 + t];
        uon[b*64 + t] = (S > 0.f) ? u : 0.f;
    }
}

// ---------------- similarity ----------------
__global__ void sim_kernel(const float* __restrict__ emb, const float* __restrict__ uon,
                           const float* __restrict__ bg2, const int* __restrict__ mask,
                           float* __restrict__ partial)
{
    __shared__ float ps[8];
    int w = threadIdx.x >> 5, lane = threadIdx.x & 31;
    int row = blockIdx.x * 8 + w;
    float c = 0.f;
    if (row < NTOT) {
        int b = row / LL;
        float m = (float)mask[row];
        float e0 = emb[(size_t)row*64 + lane];
        float e1 = emb[(size_t)row*64 + 32 + lane];
        float g0 = m*uon[b*64 + lane]      + bg2[lane];
        float g1 = m*uon[b*64 + 32 + lane] + bg2[lane+32];
        float num = wsum(e0*g0 + e1*g1);
        float na  = wsum(e0*e0 + e1*e1);
        float nb  = wsum(g0*g0 + g1*g1);
        na = fmaxf(sqrtf(na), 1e-8f);
        nb = fmaxf(sqrtf(nb), 1e-8f);
        c = num / (na*nb);
    }
    if (lane == 0) ps[w] = c;
    __syncthreads();
    if (threadIdx.x == 0) {
        float s = 0.f;
        #pragma unroll
        for (int i = 0; i < 8; i++) s += ps[i];
        partial[blockIdx.x] = s;
    }
}

__global__ void sim_reduce(const float* __restrict__ partial, float* __restrict__ out)
{
    __shared__ float smem[256];
    float s = 0.f;
    for (int i = threadIdx.x; i < 6432; i += 256) s += partial[i];
    smem[threadIdx.x] = s;
    __syncthreads();
    for (int o = 128; o; o >>= 1) {
        if (threadIdx.x < o) smem[threadIdx.x] += smem[threadIdx.x + o];
        __syncthreads();
    }
    if (threadIdx.x == 0) out[0] = smem[0] / (float)(LL*BB);
}

// ---------------- output assembly (vectorized) ----------------
__global__ void out_kernel(const float* __restrict__ emb, const float* __restrict__ x,
                           const float* __restrict__ negE, float* __restrict__ out)
{
    int idx = blockIdx.x*256 + threadIdx.x;   // over NTOT*16 float4 units
    int r = idx >> 4, c4 = idx & 15;
    if (r >= NTOT) return;
    const float4* emb4  = (const float4*)emb;
    const float4* x4    = (const float4*)x;
    const float4* negE4 = (const float4*)negE;
    float4* out4 = (float4*)out;
    float4 e  = emb4[(size_t)r*16 + c4];
    float4 xv = x4[(size_t)r*16 + c4];
    out4[(OFF4>>2) + (size_t)r*32 + c4]      = e;
    out4[(OFF4>>2) + (size_t)r*32 + 16 + c4] = xv;
    int b = r / LL, l = r % LL;
    if (l < LL-1) {
        size_t r200 = (size_t)b*(LL-1) + l;
        out4[(OFF1>>2) + r200*16 + c4] = xv;
        out4[(OFF2>>2) + r200*16 + c4] = emb4[(size_t)(r+1)*16 + c4];
        out4[(OFF3>>2) + r200*16 + c4] = negE4[(size_t)r*16 + c4];
    }
}

// ---------------- host ----------------
template <typename T>
static void* symaddr_v(T& sym){ void* p = nullptr; cudaGetSymbolAddress(&p, sym); return p; }

extern "C" void kernel_launch(void* const* d_in, const int* in_sizes, int n_in,
                              void* d_out, int out_size)
{
    const float* inter = (const float*)d_in[0];
    const float* neg   = (const float*)d_in[1];
    const float* fc_w  = (const float*)d_in[2];
    const float* fc_b  = (const float*)d_in[3];
    const float* mlp_w = (const float*)d_in[4];
    const float* mlp_b = (const float*)d_in[5];
    const float* pos   = (const float*)d_in[6];
    const float* ln0g  = (const float*)d_in[7];
    const float* ln0b  = (const float*)d_in[8];
    const float* wqkv  = (const float*)d_in[9];
    const float* bqkv  = (const float*)d_in[10];
    const float* wo    = (const float*)d_in[11];
    const float* bo    = (const float*)d_in[12];
    const float* ln1g  = (const float*)d_in[13];
    const float* ln1b  = (const float*)d_in[14];
    const float* w1    = (const float*)d_in[15];
    const float* b1    = (const float*)d_in[16];
    const float* w2    = (const float*)d_in[17];
    const float* b2    = (const float*)d_in[18];
    const float* ln2g  = (const float*)d_in[19];
    const float* ln2b  = (const float*)d_in[20];
    const float* wg1   = (const float*)d_in[21];
    const float* bg1   = (const float*)d_in[22];
    const float* wg2   = (const float*)d_in[23];
    const float* bg2   = (const float*)d_in[24];
    const int*   mask  = (const int*)d_in[25];
    float* out = (float*)d_out;

    float* T1   = (float*)symaddr_v(g_T1);
    float* Tneg = (float*)symaddr_v(g_Tneg);
    float* emb  = (float*)symaddr_v(g_emb);
    float* negE = (float*)symaddr_v(g_negE);
    float* x    = (float*)symaddr_v(g_x);
    float* qkvb = (float*)symaddr_v(g_qkv);
    float* attO = (float*)symaddr_v(g_attn);
    float* ff1  = (float*)symaddr_v(g_ff1);
    float* Xs3  = (float*)symaddr_v(g_xsum3);
    float* uon  = (float*)symaddr_v(g_uon);
    float* part = (float*)symaddr_v(g_part);
    __nv_bfloat16* WHi = (__nv_bfloat16*)symaddr_v(g_WHi);
    __nv_bfloat16* WLo = (__nv_bfloat16*)symaddr_v(g_WLo);

    const int SMEM_W = (2*128*72 + 2*64*72) * 2;  // 55296
    const int SMEM_A = (8*204*8 + 8*256 + 64 + 201*33*2 + 201) * 4; // 114540

    cudaFuncSetAttribute((const void*)gemm_w<1536,64,0>,
                         cudaFuncAttributeMaxDynamicSharedMemorySize, SMEM_W);
    cudaFuncSetAttribute((const void*)gemm_w<64,64,4>,
                         cudaFuncAttributeMaxDynamicSharedMemorySize, SMEM_W);
    cudaFuncSetAttribute((const void*)gemm_w<64,192,0>,
                         cudaFuncAttributeMaxDynamicSharedMemorySize, SMEM_W);
    cudaFuncSetAttribute((const void*)gemm_w<64,64,2>,
                         cudaFuncAttributeMaxDynamicSharedMemorySize, SMEM_W);
    cudaFuncSetAttribute((const void*)gemm_w<64,256,1>,
                         cudaFuncAttributeMaxDynamicSharedMemorySize, SMEM_W);
    cudaFuncSetAttribute((const void*)gemm_w<256,64,2>,
                         cudaFuncAttributeMaxDynamicSharedMemorySize, SMEM_W);
    cudaFuncSetAttribute((const void*)attn_kernel,
                         cudaFuncAttributeMaxDynamicSharedMemorySize, SMEM_A);

    const int GT = NTOT/128;   // 402
    const int GL = NTOT/8;     // 6432

    // merged weight conversion
    wconv_all<<<(WTOT+255)/256, 256>>>(fc_w, mlp_w, wqkv, wo, w1, w2, WHi, WLo);

    // both towers in one launch (grid 804)
    gemm_w<1536,64,0><<<dim3(2*GT,1), 256, SMEM_W>>>(inter, neg, WHi+OFC, WLo+OFC, fc_b,
            nullptr, nullptr, nullptr, nullptr, T1, nullptr, Tneg);
    // both mlp heads in one launch: emb=gelu(T1@mlp), x=LN(emb+pos); negE=gelu(Tneg@mlp)
    gemm_w<64,64,4><<<dim3(2*GT,1), 256, SMEM_W>>>(T1, Tneg, WHi+OMLP, WLo+OMLP, mlp_b,
            nullptr, ln0g, ln0b, pos, emb, x, negE);

    // collapsed GNN + similarity
    xsum_kernel<<<dim3(BB,3), 384>>>(inter, mask, Xs3);
    gnn_kernel<<<BB, 256>>>(Xs3, mask, wg1, bg1, wg2, uon);
    sim_kernel<<<GL, 256>>>(emb, uon, bg2, mask, part);
    sim_reduce<<<1, 256>>>(part, out + SIMO);

    // encoder (LN fused into wo / w2 epilogues)
    for (int i = 0; i < 2; i++) {
        gemm_w<64,192,0><<<dim3(GT,3), 256, SMEM_W>>>(x, nullptr, WHi+OQKV+(size_t)i*12288,
                WLo+OQKV+(size_t)i*12288, bqkv + i*192,
                nullptr, nullptr, nullptr, nullptr, qkvb, nullptr, nullptr);
        attn_kernel<<<BB*NHD, 256, SMEM_A>>>(qkvb, mask, attO);
        gemm_w<64,64,2><<<dim3(GT,1), 256, SMEM_W>>>(attO, nullptr, WHi+OWO+(size_t)i*4096,
                WLo+OWO+(size_t)i*4096, bo + i*64,
                x, ln1g + i*64, ln1b + i*64, nullptr, x, nullptr, nullptr);
        gemm_w<64,256,1><<<dim3(GT,4), 256, SMEM_W>>>(x, nullptr, WHi+OW1+(size_t)i*16384,
                WLo+OW1+(size_t)i*16384, b1 + i*256,
                nullptr, nullptr, nullptr, nullptr, ff1, nullptr, nullptr);
        gemm_w<256,64,2><<<dim3(GT,1), 256, SMEM_W>>>(ff1, nullptr, WHi+OW2+(size_t)i*16384,
                WLo+OW2+(size_t)i*16384, b2 + i*64,
                x, ln2g + i*64, ln2b + i*64, nullptr, x, nullptr, nullptr);
    }

    out_kernel<<<(NTOT*16+255)/256, 256>>>(emb, x, negE, out);
}